// round 1
// baseline (speedup 1.0000x reference)
#include <cuda_runtime.h>

#define NN 50000
#define EE 800000
#define ETOT (EE + NN)          // 850000
#define FIN 128
#define HID 32
#define HEADS 4
#define F1 128                  // HEADS*HID
#define OUTC 32

// ---- scratch (no allocs allowed) ----
__device__ float g_xl1[NN * F1];        // layer1 transformed features
__device__ float g_asrc1[NN * HEADS];
__device__ float g_adst1[NN * HEADS];
__device__ float g_den1[NN * HEADS];
__device__ float g_out1[NN * F1];       // unnormalized layer1 aggregation
__device__ float g_xl2[NN * OUTC];
__device__ float g_asrc2[NN];
__device__ float g_adst2[NN];
__device__ float g_den2[NN];
__device__ float g_easum;
__device__ float g_coef1[HEADS];
__device__ float g_coef2;

// ---------------------------------------------------------------------------
__global__ void k_zero(float* __restrict__ out) {
    int stride = gridDim.x * blockDim.x;
    int t0 = blockIdx.x * blockDim.x + threadIdx.x;
    for (int i = t0; i < NN * F1; i += stride) g_out1[i] = 0.f;
    for (int i = t0; i < NN * OUTC; i += stride) out[i] = 0.f;
    for (int i = t0; i < NN * HEADS; i += stride) g_den1[i] = 0.f;
    for (int i = t0; i < NN; i += stride) g_den2[i] = 0.f;
    if (t0 == 0) g_easum = 0.f;
}

// ---------------------------------------------------------------------------
__global__ void k_easum(const float* __restrict__ ea) {
    float s = 0.f;
    int stride = gridDim.x * blockDim.x;
    for (int i = blockIdx.x * blockDim.x + threadIdx.x; i < EE; i += stride)
        s += ea[i];
    for (int o = 16; o; o >>= 1) s += __shfl_xor_sync(0xffffffffu, s, o);
    __shared__ float sh[8];
    if ((threadIdx.x & 31) == 0) sh[threadIdx.x >> 5] = s;
    __syncthreads();
    if (threadIdx.x < 8) {
        float v = sh[threadIdx.x];
        for (int o = 4; o; o >>= 1) v += __shfl_xor_sync(0xffu, v, o);
        if (threadIdx.x == 0) atomicAdd(&g_easum, v);
    }
}

// coef1[h] = sum_c lin1_edge_w[h*32+c]*att1_edge[h*32+c];  coef2 likewise
__global__ void k_coef(const float* __restrict__ l1e, const float* __restrict__ a1e,
                       const float* __restrict__ l2e, const float* __restrict__ a2e) {
    int t = threadIdx.x;   // 128 threads
    float v = l1e[t] * a1e[t];
    for (int o = 16; o; o >>= 1) v += __shfl_xor_sync(0xffffffffu, v, o);
    if ((t & 31) == 0) g_coef1[t >> 5] = v;
    if (t < 32) {
        float v2 = l2e[t] * a2e[t];
        for (int o = 16; o; o >>= 1) v2 += __shfl_xor_sync(0xffffffffu, v2, o);
        if (t == 0) g_coef2 = v2;
    }
}

// ---------------------------------------------------------------------------
// xl1 = x @ W1 (128x128), plus per-head attention dots.
// Block: 128 threads, 8 nodes. x tile transposed in SMEM -> warp-uniform
// float4 reads feed 8 FFMA per single W load.
__global__ void __launch_bounds__(128) k_lin1(
    const float* __restrict__ x, const float* __restrict__ w,
    const float* __restrict__ aw_src, const float* __restrict__ aw_dst) {
    __shared__ float sxT[FIN * 8];   // [k][node]
    int t = threadIdx.x;
    int nbase = blockIdx.x * 8;
    #pragma unroll
    for (int j = 0; j < 8; j++)
        sxT[t * 8 + j] = x[(nbase + j) * FIN + t];
    __syncthreads();

    float acc[8];
    #pragma unroll
    for (int j = 0; j < 8; j++) acc[j] = 0.f;
    const int col = t;
    #pragma unroll 8
    for (int k = 0; k < FIN; k++) {
        float wv = w[k * F1 + col];
        float4 a = *(const float4*)&sxT[k * 8];
        float4 b = *(const float4*)&sxT[k * 8 + 4];
        acc[0] += a.x * wv; acc[1] += a.y * wv; acc[2] += a.z * wv; acc[3] += a.w * wv;
        acc[4] += b.x * wv; acc[5] += b.y * wv; acc[6] += b.z * wv; acc[7] += b.w * wv;
    }

    float sA = aw_src[col], sD = aw_dst[col];
    int h = col >> 5;
    #pragma unroll
    for (int j = 0; j < 8; j++) {
        int n = nbase + j;
        g_xl1[n * F1 + col] = acc[j];
        float va = acc[j] * sA, vd = acc[j] * sD;
        for (int o = 16; o; o >>= 1) {
            va += __shfl_xor_sync(0xffffffffu, va, o);
            vd += __shfl_xor_sync(0xffffffffu, vd, o);
        }
        if ((col & 31) == 0) {
            g_asrc1[n * HEADS + h] = va;
            g_adst1[n * HEADS + h] = vd;
        }
    }
}

// ---------------------------------------------------------------------------
// Fused edge pass layer1: ex = exp(lrelu(alpha)); den1[dst,h] += ex;
// out1[dst,:] += ex * xl1[src,:]. One warp per edge; lane l -> head l/8,
// feature chunk [4l, 4l+4).
__global__ void __launch_bounds__(256) k_edge1(const int* __restrict__ eidx,
                                               const float* __restrict__ eattr) {
    int w = (blockIdx.x * blockDim.x + threadIdx.x) >> 5;
    if (w >= ETOT) return;
    int l = threadIdx.x & 31;
    int s, d; float ea;
    if (w < EE) { s = eidx[w]; d = eidx[EE + w]; ea = eattr[w]; }
    else        { s = w - EE;  d = s;            ea = g_easum * (1.0f / EE); }
    int h = l >> 3;
    float alpha = g_asrc1[s * HEADS + h] + g_adst1[d * HEADS + h] + ea * g_coef1[h];
    alpha = alpha > 0.f ? alpha : 0.2f * alpha;
    float ex = __expf(alpha);
    if ((l & 7) == 0) atomicAdd(&g_den1[d * HEADS + h], ex);
    float4 xv = *(const float4*)&g_xl1[s * F1 + l * 4];
    float* ob = &g_out1[d * F1 + l * 4];
    atomicAdd(ob + 0, ex * xv.x);
    atomicAdd(ob + 1, ex * xv.y);
    atomicAdd(ob + 2, ex * xv.z);
    atomicAdd(ob + 3, ex * xv.w);
}

// ---------------------------------------------------------------------------
// h = elu(out1/den1 + bias1); xl2 = h @ W2 (128x32); attention dots.
// Warp per node; lane = out column; h broadcast via shuffle.
__global__ void __launch_bounds__(256) k_lin2(
    const float* __restrict__ w2, const float* __restrict__ bias1,
    const float* __restrict__ a2s, const float* __restrict__ a2d) {
    int n = (blockIdx.x * blockDim.x + threadIdx.x) >> 5;
    if (n >= NN) return;
    int c = threadIdx.x & 31;

    float hreg[4];
    #pragma unroll
    for (int j = 0; j < 4; j++) {
        int k = j * 32 + c;
        float v = g_out1[n * F1 + k] / g_den1[n * HEADS + j] + bias1[k];
        hreg[j] = v > 0.f ? v : expm1f(v);
    }
    float acc = 0.f;
    #pragma unroll
    for (int j = 0; j < 4; j++) {
        #pragma unroll
        for (int kk = 0; kk < 32; kk++) {
            float hk = __shfl_sync(0xffffffffu, hreg[j], kk);
            acc += hk * w2[(j * 32 + kk) * OUTC + c];
        }
    }
    g_xl2[n * OUTC + c] = acc;
    float vs = acc * a2s[c], vd = acc * a2d[c];
    for (int o = 16; o; o >>= 1) {
        vs += __shfl_xor_sync(0xffffffffu, vs, o);
        vd += __shfl_xor_sync(0xffffffffu, vd, o);
    }
    if (c == 0) { g_asrc2[n] = vs; g_adst2[n] = vd; }
}

// ---------------------------------------------------------------------------
// Fused edge pass layer2: den2[dst] += ex; out[dst,:] += ex * xl2[src,:].
__global__ void __launch_bounds__(256) k_edge2(const int* __restrict__ eidx,
                                               const float* __restrict__ eattr,
                                               float* __restrict__ out) {
    int w = (blockIdx.x * blockDim.x + threadIdx.x) >> 5;
    if (w >= ETOT) return;
    int l = threadIdx.x & 31;
    int s, d; float ea;
    if (w < EE) { s = eidx[w]; d = eidx[EE + w]; ea = eattr[w]; }
    else        { s = w - EE;  d = s;            ea = g_easum * (1.0f / EE); }
    float alpha = g_asrc2[s] + g_adst2[d] + ea * g_coef2;
    alpha = alpha > 0.f ? alpha : 0.2f * alpha;
    float ex = __expf(alpha);
    if (l == 0) atomicAdd(&g_den2[d], ex);
    atomicAdd(&out[d * OUTC + l], ex * g_xl2[s * OUTC + l]);
}

// ---------------------------------------------------------------------------
__global__ void k_final(float* __restrict__ out, const float* __restrict__ bias2) {
    int stride = gridDim.x * blockDim.x;
    for (int i = blockIdx.x * blockDim.x + threadIdx.x; i < NN * OUTC; i += stride)
        out[i] = out[i] / g_den2[i >> 5] + bias2[i & 31];
}

// ---------------------------------------------------------------------------
extern "C" void kernel_launch(void* const* d_in, const int* in_sizes, int n_in,
                              void* d_out, int out_size) {
    const float* x        = (const float*)d_in[0];
    const int*   eidx     = (const int*)  d_in[1];
    const float* eattr    = (const float*)d_in[2];
    const float* lin1_w   = (const float*)d_in[3];
    const float* att1_src = (const float*)d_in[4];
    const float* att1_dst = (const float*)d_in[5];
    const float* lin1_ew  = (const float*)d_in[6];
    const float* att1_e   = (const float*)d_in[7];
    const float* bias1    = (const float*)d_in[8];
    const float* lin2_w   = (const float*)d_in[9];
    const float* att2_src = (const float*)d_in[10];
    const float* att2_dst = (const float*)d_in[11];
    const float* lin2_ew  = (const float*)d_in[12];
    const float* att2_e   = (const float*)d_in[13];
    const float* bias2    = (const float*)d_in[14];
    float* out = (float*)d_out;

    k_zero<<<2048, 256>>>(out);
    k_easum<<<512, 256>>>(eattr);
    k_coef<<<1, 128>>>(lin1_ew, att1_e, lin2_ew, att2_e);
    k_lin1<<<NN / 8, 128>>>(x, lin1_w, att1_src, att1_dst);
    k_edge1<<<ETOT / 8, 256>>>(eidx, eattr);
    k_lin2<<<NN / 8, 256>>>(lin2_w, bias1, att2_src, att2_dst);
    k_edge2<<<ETOT / 8, 256>>>(eidx, eattr, out);
    k_final<<<2048, 256>>>(out, bias2);
}

// round 2
// speedup vs baseline: 1.4997x; 1.4997x over previous
#include <cuda_runtime.h>

#define NN 50000
#define EE 800000
#define ETOT (EE + NN)          // 850000
#define FIN 128
#define HID 32
#define HEADS 4
#define F1 128                  // HEADS*HID
#define OUTC 32

// ---- scratch (no allocs allowed) ----
__device__ float g_xl1[NN * F1];        // layer1 transformed features
__device__ float g_h1[NN * F1];         // elu(normalized layer1 out + bias1)
__device__ float g_asrc1[NN * HEADS];
__device__ float g_adst1[NN * HEADS];
__device__ float g_xl2[NN * OUTC];
__device__ float g_asrc2[NN];
__device__ float g_adst2[NN];
__device__ float g_easum;
__device__ float g_coef1[HEADS];
__device__ float g_coef2;
// CSR build
__device__ int  g_cnt[NN];
__device__ int  g_off[NN + 1];
__device__ int  g_cur[NN];
__device__ int2 g_es[ETOT];             // dst-sorted (src, ea_bits)

// ---------------------------------------------------------------------------
__global__ void k_zero() {
    int stride = gridDim.x * blockDim.x;
    int t0 = blockIdx.x * blockDim.x + threadIdx.x;
    for (int i = t0; i < NN; i += stride) g_cnt[i] = 0;
    if (t0 == 0) g_easum = 0.f;
}

// ---------------------------------------------------------------------------
__global__ void k_easum(const float* __restrict__ ea) {
    float s = 0.f;
    int stride = gridDim.x * blockDim.x;
    for (int i = blockIdx.x * blockDim.x + threadIdx.x; i < EE; i += stride)
        s += ea[i];
    for (int o = 16; o; o >>= 1) s += __shfl_xor_sync(0xffffffffu, s, o);
    __shared__ float sh[8];
    if ((threadIdx.x & 31) == 0) sh[threadIdx.x >> 5] = s;
    __syncthreads();
    if (threadIdx.x < 8) {
        float v = sh[threadIdx.x];
        for (int o = 4; o; o >>= 1) v += __shfl_xor_sync(0xffu, v, o);
        if (threadIdx.x == 0) atomicAdd(&g_easum, v);
    }
}

// coef1[h] = sum_c lin1_edge_w[h*32+c]*att1_edge[h*32+c];  coef2 likewise
__global__ void k_coef(const float* __restrict__ l1e, const float* __restrict__ a1e,
                       const float* __restrict__ l2e, const float* __restrict__ a2e) {
    int t = threadIdx.x;   // 128 threads
    float v = l1e[t] * a1e[t];
    for (int o = 16; o; o >>= 1) v += __shfl_xor_sync(0xffffffffu, v, o);
    if ((t & 31) == 0) g_coef1[t >> 5] = v;
    if (t < 32) {
        float v2 = l2e[t] * a2e[t];
        for (int o = 16; o; o >>= 1) v2 += __shfl_xor_sync(0xffffffffu, v2, o);
        if (t == 0) g_coef2 = v2;
    }
}

// ---------------------------------------------------------------------------
// CSR build: histogram -> scan -> scatter
__global__ void k_hist(const int* __restrict__ eidx) {
    int i = blockIdx.x * blockDim.x + threadIdx.x;
    if (i >= ETOT) return;
    int d = (i < EE) ? eidx[EE + i] : (i - EE);
    atomicAdd(&g_cnt[d], 1);
}

__global__ void __launch_bounds__(1024) k_scan() {
    // single block, 1024 threads; each thread owns a contiguous chunk
    __shared__ int wsum[32];
    const int per = (NN + 1023) / 1024;   // 49
    int t = threadIdx.x, lane = t & 31, w = t >> 5;
    int base = t * per;
    int lim = min(base + per, NN);
    int s = 0;
    for (int i = base; i < lim; i++) s += g_cnt[i];
    // inclusive scan of s across block
    int inc = s;
    #pragma unroll
    for (int o = 1; o < 32; o <<= 1) {
        int v = __shfl_up_sync(0xffffffffu, inc, o);
        if (lane >= o) inc += v;
    }
    if (lane == 31) wsum[w] = inc;
    __syncthreads();
    if (w == 0) {
        int v = (lane < 32) ? wsum[lane] : 0;
        int iv = v;
        #pragma unroll
        for (int o = 1; o < 32; o <<= 1) {
            int u = __shfl_up_sync(0xffffffffu, iv, o);
            if (lane >= o) iv += u;
        }
        wsum[lane] = iv - v;   // exclusive warp-prefix
    }
    __syncthreads();
    int running = inc - s + wsum[w];   // exclusive prefix for this thread
    for (int i = base; i < lim; i++) {
        g_off[i] = running;
        g_cur[i] = running;
        running += g_cnt[i];
    }
    if (t == 0) g_off[NN] = ETOT;
}

__global__ void k_scatter(const int* __restrict__ eidx, const float* __restrict__ eattr) {
    int i = blockIdx.x * blockDim.x + threadIdx.x;
    if (i >= ETOT) return;
    int s, d; float ea;
    if (i < EE) { s = eidx[i]; d = eidx[EE + i]; ea = eattr[i]; }
    else        { s = i - EE;  d = s;            ea = g_easum * (1.0f / EE); }
    int pos = atomicAdd(&g_cur[d], 1);
    g_es[pos] = make_int2(s, __float_as_int(ea));
}

// ---------------------------------------------------------------------------
// xl1 = x @ W1 (128x128). 32 nodes/block, 128 threads. x tile transposed in
// SMEM (pad 36 -> float4-aligned, conflict-light) so each W load feeds 32 FFMA.
__global__ void __launch_bounds__(128) k_lin1(
    const float* __restrict__ x, const float* __restrict__ w) {
    __shared__ float sxT[FIN * 36];   // [k][node(+pad)]
    int t = threadIdx.x;
    int lane = t & 31, wid = t >> 5;
    int nbase = blockIdx.x * 32;

    #pragma unroll
    for (int jj = 0; jj < 8; jj++) {
        int j = wid * 8 + jj;
        int n = nbase + j;
        const float* xr = x + (long)min(n, NN - 1) * FIN;
        #pragma unroll
        for (int c = 0; c < 4; c++) {
            int k = c * 32 + lane;
            sxT[k * 36 + j] = (n < NN) ? xr[k] : 0.f;
        }
    }
    __syncthreads();

    float acc[32];
    #pragma unroll
    for (int j = 0; j < 32; j++) acc[j] = 0.f;
    const int col = t;
    #pragma unroll 4
    for (int k = 0; k < FIN; k++) {
        float wv = w[k * F1 + col];
        #pragma unroll
        for (int jg = 0; jg < 8; jg++) {
            float4 v = *(const float4*)&sxT[k * 36 + jg * 4];
            acc[jg * 4 + 0] += v.x * wv;
            acc[jg * 4 + 1] += v.y * wv;
            acc[jg * 4 + 2] += v.z * wv;
            acc[jg * 4 + 3] += v.w * wv;
        }
    }
    #pragma unroll
    for (int j = 0; j < 32; j++) {
        int n = nbase + j;
        if (n < NN) g_xl1[(long)n * F1 + col] = acc[j];
    }
}

// attention dots for layer1: warp per node
__global__ void __launch_bounds__(256) k_att1(const float* __restrict__ a1s,
                                              const float* __restrict__ a1d) {
    int n = blockIdx.x * 8 + (threadIdx.x >> 5);
    if (n >= NN) return;
    int l = threadIdx.x & 31;
    float vs[4], vd[4];
    #pragma unroll
    for (int h = 0; h < 4; h++) {
        float xv = g_xl1[(long)n * F1 + h * 32 + l];
        vs[h] = xv * a1s[h * 32 + l];
        vd[h] = xv * a1d[h * 32 + l];
    }
    #pragma unroll
    for (int h = 0; h < 4; h++)
        for (int o = 16; o; o >>= 1) {
            vs[h] += __shfl_xor_sync(0xffffffffu, vs[h], o);
            vd[h] += __shfl_xor_sync(0xffffffffu, vd[h], o);
        }
    if (l == 0) {
        #pragma unroll
        for (int h = 0; h < 4; h++) {
            g_asrc1[n * HEADS + h] = vs[h];
            g_adst1[n * HEADS + h] = vd[h];
        }
    }
}

// ---------------------------------------------------------------------------
// Gather edge pass layer1: warp per dst node, no atomics.
// lane l -> head l/8, feature chunk [4l,4l+4). All 8 lanes of a head compute
// identical ex -> den needs no cross-lane reduction.
// Epilogue fuses: normalize + bias1 + ELU -> g_h1.
__global__ void __launch_bounds__(256) k_edge1g(const float* __restrict__ bias1) {
    int d = blockIdx.x * 8 + (threadIdx.x >> 5);
    if (d >= NN) return;
    int l = threadIdx.x & 31;
    int h = l >> 3;
    int beg = g_off[d], end = g_off[d + 1];
    float adst = g_adst1[d * HEADS + h];
    float cf = g_coef1[h];
    float4 acc = make_float4(0.f, 0.f, 0.f, 0.f);
    float den = 0.f;
    for (int j = beg; j < end; j++) {
        int2 e = g_es[j];
        int s = e.x;
        float ea = __int_as_float(e.y);
        float alpha = g_asrc1[s * HEADS + h] + adst + ea * cf;
        alpha = alpha > 0.f ? alpha : 0.2f * alpha;
        float ex = __expf(alpha);
        den += ex;
        float4 xv = *(const float4*)&g_xl1[(long)s * F1 + l * 4];
        acc.x += ex * xv.x; acc.y += ex * xv.y;
        acc.z += ex * xv.z; acc.w += ex * xv.w;
    }
    float inv = 1.f / den;
    float4 b = *(const float4*)&bias1[l * 4];
    float4 v;
    v.x = acc.x * inv + b.x; v.y = acc.y * inv + b.y;
    v.z = acc.z * inv + b.z; v.w = acc.w * inv + b.w;
    v.x = v.x > 0.f ? v.x : expm1f(v.x);
    v.y = v.y > 0.f ? v.y : expm1f(v.y);
    v.z = v.z > 0.f ? v.z : expm1f(v.z);
    v.w = v.w > 0.f ? v.w : expm1f(v.w);
    *(float4*)&g_h1[(long)d * F1 + l * 4] = v;
}

// ---------------------------------------------------------------------------
// xl2 = h1 @ W2 (128x32) + attention dots. Warp per node, W2 staged in smem.
__global__ void __launch_bounds__(256) k_lin2(
    const float* __restrict__ w2, const float* __restrict__ a2s,
    const float* __restrict__ a2d) {
    __shared__ float sw2[F1 * OUTC];
    for (int i = threadIdx.x; i < F1 * OUTC; i += 256) sw2[i] = w2[i];
    __syncthreads();
    int n = blockIdx.x * 8 + (threadIdx.x >> 5);
    if (n >= NN) return;
    int c = threadIdx.x & 31;

    float hreg[4];
    #pragma unroll
    for (int j = 0; j < 4; j++) hreg[j] = g_h1[(long)n * F1 + j * 32 + c];
    float acc = 0.f;
    #pragma unroll
    for (int j = 0; j < 4; j++) {
        #pragma unroll
        for (int kk = 0; kk < 32; kk++) {
            float hk = __shfl_sync(0xffffffffu, hreg[j], kk);
            acc += hk * sw2[(j * 32 + kk) * OUTC + c];
        }
    }
    g_xl2[n * OUTC + c] = acc;
    float vs = acc * a2s[c], vd = acc * a2d[c];
    for (int o = 16; o; o >>= 1) {
        vs += __shfl_xor_sync(0xffffffffu, vs, o);
        vd += __shfl_xor_sync(0xffffffffu, vd, o);
    }
    if (c == 0) { g_asrc2[n] = vs; g_adst2[n] = vd; }
}

// ---------------------------------------------------------------------------
// Gather edge pass layer2: warp per dst node; lane = out col; fused bias.
__global__ void __launch_bounds__(256) k_edge2g(float* __restrict__ out,
                                                const float* __restrict__ bias2) {
    int d = blockIdx.x * 8 + (threadIdx.x >> 5);
    if (d >= NN) return;
    int l = threadIdx.x & 31;
    int beg = g_off[d], end = g_off[d + 1];
    float adst = g_adst2[d];
    float cf = g_coef2;
    float acc = 0.f, den = 0.f;
    for (int j = beg; j < end; j++) {
        int2 e = g_es[j];
        int s = e.x;
        float ea = __int_as_float(e.y);
        float alpha = g_asrc2[s] + adst + ea * cf;
        alpha = alpha > 0.f ? alpha : 0.2f * alpha;
        float ex = __expf(alpha);
        den += ex;
        acc += ex * g_xl2[s * OUTC + l];
    }
    out[(long)d * OUTC + l] = acc / den + bias2[l];
}

// ---------------------------------------------------------------------------
extern "C" void kernel_launch(void* const* d_in, const int* in_sizes, int n_in,
                              void* d_out, int out_size) {
    const float* x        = (const float*)d_in[0];
    const int*   eidx     = (const int*)  d_in[1];
    const float* eattr    = (const float*)d_in[2];
    const float* lin1_w   = (const float*)d_in[3];
    const float* att1_src = (const float*)d_in[4];
    const float* att1_dst = (const float*)d_in[5];
    const float* lin1_ew  = (const float*)d_in[6];
    const float* att1_e   = (const float*)d_in[7];
    const float* bias1    = (const float*)d_in[8];
    const float* lin2_w   = (const float*)d_in[9];
    const float* att2_src = (const float*)d_in[10];
    const float* att2_dst = (const float*)d_in[11];
    const float* lin2_ew  = (const float*)d_in[12];
    const float* att2_e   = (const float*)d_in[13];
    const float* bias2    = (const float*)d_in[14];
    float* out = (float*)d_out;

    k_zero<<<256, 256>>>();
    k_easum<<<512, 256>>>(eattr);
    k_coef<<<1, 128>>>(lin1_ew, att1_e, lin2_ew, att2_e);
    k_hist<<<(ETOT + 255) / 256, 256>>>(eidx);
    k_scan<<<1, 1024>>>();
    k_scatter<<<(ETOT + 255) / 256, 256>>>(eidx, eattr);
    k_lin1<<<(NN + 31) / 32, 128>>>(x, lin1_w);
    k_att1<<<(NN + 7) / 8, 256>>>(att1_src, att1_dst);
    k_edge1g<<<(NN + 7) / 8, 256>>>(bias1);
    k_lin2<<<(NN + 7) / 8, 256>>>(lin2_w, att2_src, att2_dst);
    k_edge2g<<<(NN + 7) / 8, 256>>>(out, bias2);
}

// round 3
// speedup vs baseline: 1.5439x; 1.0295x over previous
#include <cuda_runtime.h>
#include <cuda_fp16.h>

#define NN 50000
#define EE 800000
#define ETOT (EE + NN)          // 850000
#define FIN 128
#define HID 32
#define HEADS 4
#define F1 128                  // HEADS*HID
#define OUTC 32

// ---- scratch (no allocs allowed) ----
__device__ __half g_xl1h[NN * F1];      // layer1 transformed features (fp16)
__device__ float g_h1[NN * F1];         // elu(normalized layer1 out + bias1)
__device__ float g_asrc1[NN * HEADS];
__device__ float g_adst1[NN * HEADS];
__device__ float g_xl2[NN * OUTC];
__device__ float g_asrc2[NN];
__device__ float g_adst2[NN];
__device__ float g_part[512];
__device__ float g_loopea;              // easum / EE
__device__ float g_coef1[HEADS];
__device__ float g_coef2;
// CSR build
__device__ int  g_cnt[NN];
__device__ int  g_off[NN + 1];
__device__ int  g_cur[NN];
__device__ int2 g_es[ETOT];             // dst-sorted (src, ea_bits)

#define FMA2(d, a, b) asm("fma.rn.f32x2 %0, %1, %2, %0;" : "+l"(d) : "l"(a), "l"(b))

// ---------------------------------------------------------------------------
// prep: zero cnt, easum partials, coef dots
__global__ void __launch_bounds__(256) k_prep(
    const float* __restrict__ ea,
    const float* __restrict__ l1e, const float* __restrict__ a1e,
    const float* __restrict__ l2e, const float* __restrict__ a2e) {
    int t0 = blockIdx.x * blockDim.x + threadIdx.x;
    int stride = gridDim.x * blockDim.x;
    for (int i = t0; i < NN; i += stride) g_cnt[i] = 0;

    float s = 0.f;
    for (int i = t0; i < EE; i += stride) s += ea[i];
    for (int o = 16; o; o >>= 1) s += __shfl_xor_sync(0xffffffffu, s, o);
    __shared__ float sh[8];
    if ((threadIdx.x & 31) == 0) sh[threadIdx.x >> 5] = s;
    __syncthreads();
    if (threadIdx.x < 8) {
        float v = sh[threadIdx.x];
        for (int o = 4; o; o >>= 1) v += __shfl_xor_sync(0xffu, v, o);
        if (threadIdx.x == 0) g_part[blockIdx.x] = v;
    }

    if (blockIdx.x == 0 && threadIdx.x < 128) {
        int t = threadIdx.x;
        float v = l1e[t] * a1e[t];
        for (int o = 16; o; o >>= 1) v += __shfl_xor_sync(0xffffffffu, v, o);
        if ((t & 31) == 0) g_coef1[t >> 5] = v;
        if (t < 32) {
            float v2 = l2e[t] * a2e[t];
            for (int o = 16; o; o >>= 1) v2 += __shfl_xor_sync(0xffffffffu, v2, o);
            if (t == 0) g_coef2 = v2;
        }
    }
}

// ---------------------------------------------------------------------------
__global__ void k_hist(const int* __restrict__ eidx) {
    int i = blockIdx.x * blockDim.x + threadIdx.x;
    if (i >= ETOT) return;
    int d = (i < EE) ? eidx[EE + i] : (i - EE);
    atomicAdd(&g_cnt[d], 1);
}

// single block: finalize easum + exclusive scan of counts
__global__ void __launch_bounds__(1024) k_scan() {
    int t = threadIdx.x, lane = t & 31, w = t >> 5;

    // easum finalize (512 partials)
    __shared__ float esh[32];
    float ev = (t < 512) ? g_part[t] : 0.f;
    for (int o = 16; o; o >>= 1) ev += __shfl_xor_sync(0xffffffffu, ev, o);
    if (lane == 0) esh[w] = ev;
    __syncthreads();
    if (w == 0) {
        float v = esh[lane];
        for (int o = 16; o; o >>= 1) v += __shfl_xor_sync(0xffffffffu, v, o);
        if (lane == 0) g_loopea = v * (1.0f / EE);
    }

    // scan
    __shared__ int wsum[32];
    const int per = (NN + 1023) / 1024;   // 49
    int base = t * per;
    int lim = min(base + per, NN);
    int s = 0;
    for (int i = base; i < lim; i++) s += g_cnt[i];
    int inc = s;
    #pragma unroll
    for (int o = 1; o < 32; o <<= 1) {
        int v = __shfl_up_sync(0xffffffffu, inc, o);
        if (lane >= o) inc += v;
    }
    if (lane == 31) wsum[w] = inc;
    __syncthreads();
    if (w == 0) {
        int v = wsum[lane];
        int iv = v;
        #pragma unroll
        for (int o = 1; o < 32; o <<= 1) {
            int u = __shfl_up_sync(0xffffffffu, iv, o);
            if (lane >= o) iv += u;
        }
        wsum[lane] = iv - v;   // exclusive warp-prefix
    }
    __syncthreads();
    int running = inc - s + wsum[w];
    for (int i = base; i < lim; i++) {
        g_off[i] = running;
        g_cur[i] = running;
        running += g_cnt[i];
    }
    if (t == 0) g_off[NN] = ETOT;
}

__global__ void k_scatter(const int* __restrict__ eidx, const float* __restrict__ eattr) {
    int i = blockIdx.x * blockDim.x + threadIdx.x;
    if (i >= ETOT) return;
    int s, d; float ea;
    if (i < EE) { s = eidx[i]; d = eidx[EE + i]; ea = eattr[i]; }
    else        { s = i - EE;  d = s;            ea = g_loopea; }
    int pos = atomicAdd(&g_cur[d], 1);
    g_es[pos] = make_int2(s, __float_as_int(ea));
}

// ---------------------------------------------------------------------------
// xl1 = x @ W1 (128x128). 32 nodes/block, 128 threads, packed f32x2 FMA.
__global__ void __launch_bounds__(128) k_lin1(
    const float* __restrict__ x, const float* __restrict__ w) {
    __shared__ float sxT[FIN * 36];   // [k][node(+pad)]
    int t = threadIdx.x;
    int lane = t & 31, wid = t >> 5;
    int nbase = blockIdx.x * 32;

    #pragma unroll
    for (int jj = 0; jj < 8; jj++) {
        int j = wid * 8 + jj;
        int n = nbase + j;
        const float* xr = x + (long)min(n, NN - 1) * FIN;
        #pragma unroll
        for (int c = 0; c < 4; c++) {
            int k = c * 32 + lane;
            sxT[k * 36 + j] = (n < NN) ? xr[k] : 0.f;
        }
    }
    __syncthreads();

    unsigned long long acc[16];   // 16 x f32x2 = 32 node accumulators
    #pragma unroll
    for (int p = 0; p < 16; p++) acc[p] = 0ull;
    const int col = t;
    #pragma unroll 4
    for (int k = 0; k < FIN; k++) {
        float wv = w[k * F1 + col];
        unsigned long long wv2;
        asm("mov.b64 %0, {%1, %1};" : "=l"(wv2) : "f"(wv));
        #pragma unroll
        for (int jg = 0; jg < 8; jg++) {
            ulonglong2 xv = *(const ulonglong2*)&sxT[k * 36 + jg * 4];
            FMA2(acc[jg * 2 + 0], xv.x, wv2);
            FMA2(acc[jg * 2 + 1], xv.y, wv2);
        }
    }
    #pragma unroll
    for (int p = 0; p < 16; p++) {
        float lo, hi;
        asm("mov.b64 {%0, %1}, %2;" : "=f"(lo), "=f"(hi) : "l"(acc[p]));
        int n0 = nbase + p * 2;
        if (n0 < NN)     g_xl1h[(long)n0 * F1 + col]       = __float2half_rn(lo);
        if (n0 + 1 < NN) g_xl1h[(long)(n0 + 1) * F1 + col] = __float2half_rn(hi);
    }
}

// attention dots for layer1: warp per node
__global__ void __launch_bounds__(256) k_att1(const float* __restrict__ a1s,
                                              const float* __restrict__ a1d) {
    int n = blockIdx.x * 8 + (threadIdx.x >> 5);
    if (n >= NN) return;
    int l = threadIdx.x & 31;
    float vs[4], vd[4];
    #pragma unroll
    for (int h = 0; h < 4; h++) {
        float xv = __half2float(g_xl1h[(long)n * F1 + h * 32 + l]);
        vs[h] = xv * a1s[h * 32 + l];
        vd[h] = xv * a1d[h * 32 + l];
    }
    #pragma unroll
    for (int h = 0; h < 4; h++)
        for (int o = 16; o; o >>= 1) {
            vs[h] += __shfl_xor_sync(0xffffffffu, vs[h], o);
            vd[h] += __shfl_xor_sync(0xffffffffu, vd[h], o);
        }
    if (l == 0) {
        #pragma unroll
        for (int h = 0; h < 4; h++) {
            g_asrc1[n * HEADS + h] = vs[h];
            g_adst1[n * HEADS + h] = vd[h];
        }
    }
}

// ---------------------------------------------------------------------------
// Gather edge pass layer1: warp per dst node, fp16 feature gather, no atomics.
// lane l -> head l/8, feature chunk [4l,4l+4).
__global__ void __launch_bounds__(256) k_edge1g(const float* __restrict__ bias1) {
    int d = blockIdx.x * 8 + (threadIdx.x >> 5);
    if (d >= NN) return;
    int l = threadIdx.x & 31;
    int h = l >> 3;
    int beg = g_off[d], end = g_off[d + 1];
    float adst = g_adst1[d * HEADS + h];
    float cf = g_coef1[h];
    float4 acc = make_float4(0.f, 0.f, 0.f, 0.f);
    float den = 0.f;
    for (int j = beg; j < end; j++) {
        int2 e = g_es[j];
        int s = e.x;
        float ea = __int_as_float(e.y);
        float alpha = g_asrc1[s * HEADS + h] + adst + ea * cf;
        alpha = alpha > 0.f ? alpha : 0.2f * alpha;
        float ex = __expf(alpha);
        den += ex;
        uint2 pv = *(const uint2*)(g_xl1h + (long)s * F1 + l * 4);
        float2 f0 = __half22float2(*reinterpret_cast<__half2*>(&pv.x));
        float2 f1 = __half22float2(*reinterpret_cast<__half2*>(&pv.y));
        acc.x += ex * f0.x; acc.y += ex * f0.y;
        acc.z += ex * f1.x; acc.w += ex * f1.y;
    }
    float inv = 1.f / den;
    float4 b = *(const float4*)&bias1[l * 4];
    float4 v;
    v.x = acc.x * inv + b.x; v.y = acc.y * inv + b.y;
    v.z = acc.z * inv + b.z; v.w = acc.w * inv + b.w;
    v.x = v.x > 0.f ? v.x : expm1f(v.x);
    v.y = v.y > 0.f ? v.y : expm1f(v.y);
    v.z = v.z > 0.f ? v.z : expm1f(v.z);
    v.w = v.w > 0.f ? v.w : expm1f(v.w);
    *(float4*)&g_h1[(long)d * F1 + l * 4] = v;
}

// ---------------------------------------------------------------------------
// xl2 = h1 @ W2 (128x32) + attention dots. Warp per node, W2 staged in smem.
__global__ void __launch_bounds__(256) k_lin2(
    const float* __restrict__ w2, const float* __restrict__ a2s,
    const float* __restrict__ a2d) {
    __shared__ float sw2[F1 * OUTC];
    for (int i = threadIdx.x; i < F1 * OUTC; i += 256) sw2[i] = w2[i];
    __syncthreads();
    int n = blockIdx.x * 8 + (threadIdx.x >> 5);
    if (n >= NN) return;
    int c = threadIdx.x & 31;

    float hreg[4];
    #pragma unroll
    for (int j = 0; j < 4; j++) hreg[j] = g_h1[(long)n * F1 + j * 32 + c];
    float acc = 0.f;
    #pragma unroll
    for (int j = 0; j < 4; j++) {
        #pragma unroll
        for (int kk = 0; kk < 32; kk++) {
            float hk = __shfl_sync(0xffffffffu, hreg[j], kk);
            acc += hk * sw2[(j * 32 + kk) * OUTC + c];
        }
    }
    g_xl2[n * OUTC + c] = acc;
    float vs = acc * a2s[c], vd = acc * a2d[c];
    for (int o = 16; o; o >>= 1) {
        vs += __shfl_xor_sync(0xffffffffu, vs, o);
        vd += __shfl_xor_sync(0xffffffffu, vd, o);
    }
    if (c == 0) { g_asrc2[n] = vs; g_adst2[n] = vd; }
}

// ---------------------------------------------------------------------------
// Gather edge pass layer2: warp per dst node; lane = out col; fused bias.
__global__ void __launch_bounds__(256) k_edge2g(float* __restrict__ out,
                                                const float* __restrict__ bias2) {
    int d = blockIdx.x * 8 + (threadIdx.x >> 5);
    if (d >= NN) return;
    int l = threadIdx.x & 31;
    int beg = g_off[d], end = g_off[d + 1];
    float adst = g_adst2[d];
    float cf = g_coef2;
    float acc = 0.f, den = 0.f;
    for (int j = beg; j < end; j++) {
        int2 e = g_es[j];
        int s = e.x;
        float ea = __int_as_float(e.y);
        float alpha = g_asrc2[s] + adst + ea * cf;
        alpha = alpha > 0.f ? alpha : 0.2f * alpha;
        float ex = __expf(alpha);
        den += ex;
        acc += ex * g_xl2[s * OUTC + l];
    }
    out[(long)d * OUTC + l] = acc / den + bias2[l];
}

// ---------------------------------------------------------------------------
extern "C" void kernel_launch(void* const* d_in, const int* in_sizes, int n_in,
                              void* d_out, int out_size) {
    const float* x        = (const float*)d_in[0];
    const int*   eidx     = (const int*)  d_in[1];
    const float* eattr    = (const float*)d_in[2];
    const float* lin1_w   = (const float*)d_in[3];
    const float* att1_src = (const float*)d_in[4];
    const float* att1_dst = (const float*)d_in[5];
    const float* lin1_ew  = (const float*)d_in[6];
    const float* att1_e   = (const float*)d_in[7];
    const float* bias1    = (const float*)d_in[8];
    const float* lin2_w   = (const float*)d_in[9];
    const float* att2_src = (const float*)d_in[10];
    const float* att2_dst = (const float*)d_in[11];
    const float* lin2_ew  = (const float*)d_in[12];
    const float* att2_e   = (const float*)d_in[13];
    const float* bias2    = (const float*)d_in[14];
    float* out = (float*)d_out;

    k_prep<<<512, 256>>>(eattr, lin1_ew, att1_e, lin2_ew, att2_e);
    k_hist<<<(ETOT + 255) / 256, 256>>>(eidx);
    k_scan<<<1, 1024>>>();
    k_scatter<<<(ETOT + 255) / 256, 256>>>(eidx, eattr);
    k_lin1<<<(NN + 31) / 32, 128>>>(x, lin1_w);
    k_att1<<<(NN + 7) / 8, 256>>>(att1_src, att1_dst);
    k_edge1g<<<(NN + 7) / 8, 256>>>(bias1);
    k_lin2<<<(NN + 7) / 8, 256>>>(lin2_w, att2_src, att2_dst);
    k_edge2g<<<(NN + 7) / 8, 256>>>(out, bias2);
}

// round 4
// speedup vs baseline: 1.5826x; 1.0250x over previous
#include <cuda_runtime.h>
#include <cuda_fp16.h>

#define NN 50000
#define EE 800000
#define ETOT (EE + NN)          // 850000
#define FIN 128
#define HID 32
#define HEADS 4
#define F1 128                  // HEADS*HID
#define OUTC 32

// ---- scratch (no allocs allowed) ----
__device__ __half g_xl1h[NN * F1];      // layer1 transformed features (fp16)
__device__ float g_h1[NN * F1];         // elu(normalized layer1 out + bias1)
__device__ __align__(16) float g_asrc1[NN * HEADS];
__device__ __align__(16) float g_adst1[NN * HEADS];
__device__ float g_xl2[NN * OUTC];
__device__ float g_asrc2[NN];
__device__ float g_adst2[NN];
__device__ float g_part[512];
__device__ float g_loopea;              // easum / EE
__device__ __align__(16) float g_coef1[4];
__device__ float g_coef2;
// CSR (SoA) + precomputed ex
__device__ int   g_cnt[NN];
__device__ int   g_off[NN + 1];
__device__ int   g_cur[NN];
__device__ int   g_esrc[ETOT];
__device__ int   g_edst[ETOT];
__device__ float g_eea[ETOT];
__device__ __align__(16) float4 g_ex1[ETOT];
__device__ float g_ex2[ETOT];

#define FMA2(d, a, b) asm("fma.rn.f32x2 %0, %1, %2, %0;" : "+l"(d) : "l"(a), "l"(b))

// ---------------------------------------------------------------------------
// prep: zero cnt, easum partials, coef dots
__global__ void __launch_bounds__(256) k_prep(
    const float* __restrict__ ea,
    const float* __restrict__ l1e, const float* __restrict__ a1e,
    const float* __restrict__ l2e, const float* __restrict__ a2e) {
    int t0 = blockIdx.x * blockDim.x + threadIdx.x;
    int stride = gridDim.x * blockDim.x;
    for (int i = t0; i < NN; i += stride) g_cnt[i] = 0;

    float s = 0.f;
    for (int i = t0; i < EE; i += stride) s += ea[i];
    for (int o = 16; o; o >>= 1) s += __shfl_xor_sync(0xffffffffu, s, o);
    __shared__ float sh[8];
    if ((threadIdx.x & 31) == 0) sh[threadIdx.x >> 5] = s;
    __syncthreads();
    if (threadIdx.x < 8) {
        float v = sh[threadIdx.x];
        for (int o = 4; o; o >>= 1) v += __shfl_xor_sync(0xffu, v, o);
        if (threadIdx.x == 0) g_part[blockIdx.x] = v;
    }

    if (blockIdx.x == 0 && threadIdx.x < 128) {
        int t = threadIdx.x;
        float v = l1e[t] * a1e[t];
        for (int o = 16; o; o >>= 1) v += __shfl_xor_sync(0xffffffffu, v, o);
        if ((t & 31) == 0) g_coef1[t >> 5] = v;
        if (t < 32) {
            float v2 = l2e[t] * a2e[t];
            for (int o = 16; o; o >>= 1) v2 += __shfl_xor_sync(0xffffffffu, v2, o);
            if (t == 0) g_coef2 = v2;
        }
    }
}

// ---------------------------------------------------------------------------
__global__ void k_hist(const int* __restrict__ eidx) {
    int i = blockIdx.x * blockDim.x + threadIdx.x;
    if (i >= ETOT) return;
    int d = (i < EE) ? eidx[EE + i] : (i - EE);
    atomicAdd(&g_cnt[d], 1);
}

// single block: finalize easum + exclusive scan of counts
__global__ void __launch_bounds__(1024) k_scan() {
    int t = threadIdx.x, lane = t & 31, w = t >> 5;

    __shared__ float esh[32];
    float ev = (t < 512) ? g_part[t] : 0.f;
    for (int o = 16; o; o >>= 1) ev += __shfl_xor_sync(0xffffffffu, ev, o);
    if (lane == 0) esh[w] = ev;
    __syncthreads();
    if (w == 0) {
        float v = esh[lane];
        for (int o = 16; o; o >>= 1) v += __shfl_xor_sync(0xffffffffu, v, o);
        if (lane == 0) g_loopea = v * (1.0f / EE);
    }

    __shared__ int wsum[32];
    const int per = (NN + 1023) / 1024;   // 49
    int base = t * per;
    int lim = min(base + per, NN);
    int s = 0;
    for (int i = base; i < lim; i++) s += g_cnt[i];
    int inc = s;
    #pragma unroll
    for (int o = 1; o < 32; o <<= 1) {
        int v = __shfl_up_sync(0xffffffffu, inc, o);
        if (lane >= o) inc += v;
    }
    if (lane == 31) wsum[w] = inc;
    __syncthreads();
    if (w == 0) {
        int v = wsum[lane];
        int iv = v;
        #pragma unroll
        for (int o = 1; o < 32; o <<= 1) {
            int u = __shfl_up_sync(0xffffffffu, iv, o);
            if (lane >= o) iv += u;
        }
        wsum[lane] = iv - v;
    }
    __syncthreads();
    int running = inc - s + wsum[w];
    for (int i = base; i < lim; i++) {
        g_off[i] = running;
        g_cur[i] = running;
        running += g_cnt[i];
    }
    if (t == 0) g_off[NN] = ETOT;
}

__global__ void k_scatter(const int* __restrict__ eidx, const float* __restrict__ eattr) {
    int i = blockIdx.x * blockDim.x + threadIdx.x;
    if (i >= ETOT) return;
    int s, d; float ea;
    if (i < EE) { s = eidx[i]; d = eidx[EE + i]; ea = eattr[i]; }
    else        { s = i - EE;  d = s;            ea = g_loopea; }
    int pos = atomicAdd(&g_cur[d], 1);
    g_esrc[pos] = s;
    g_edst[pos] = d;
    g_eea[pos] = ea;
}

// ---------------------------------------------------------------------------
// xl1 = x @ W1 (128x128). 32 nodes/block, 128 threads, packed f32x2 FMA.
__global__ void __launch_bounds__(128) k_lin1(
    const float* __restrict__ x, const float* __restrict__ w) {
    __shared__ float sxT[FIN * 36];   // [k][node(+pad)]
    int t = threadIdx.x;
    int lane = t & 31, wid = t >> 5;
    int nbase = blockIdx.x * 32;

    #pragma unroll
    for (int jj = 0; jj < 8; jj++) {
        int j = wid * 8 + jj;
        int n = nbase + j;
        const float* xr = x + (long)min(n, NN - 1) * FIN;
        #pragma unroll
        for (int c = 0; c < 4; c++) {
            int k = c * 32 + lane;
            sxT[k * 36 + j] = (n < NN) ? xr[k] : 0.f;
        }
    }
    __syncthreads();

    unsigned long long acc[16];   // 16 x f32x2 = 32 node accumulators
    #pragma unroll
    for (int p = 0; p < 16; p++) acc[p] = 0ull;
    const int col = t;
    #pragma unroll 4
    for (int k = 0; k < FIN; k++) {
        float wv = w[k * F1 + col];
        unsigned long long wv2;
        asm("mov.b64 %0, {%1, %1};" : "=l"(wv2) : "f"(wv));
        #pragma unroll
        for (int jg = 0; jg < 8; jg++) {
            ulonglong2 xv = *(const ulonglong2*)&sxT[k * 36 + jg * 4];
            FMA2(acc[jg * 2 + 0], xv.x, wv2);
            FMA2(acc[jg * 2 + 1], xv.y, wv2);
        }
    }
    #pragma unroll
    for (int p = 0; p < 16; p++) {
        float lo, hi;
        asm("mov.b64 {%0, %1}, %2;" : "=f"(lo), "=f"(hi) : "l"(acc[p]));
        int n0 = nbase + p * 2;
        if (n0 < NN)     g_xl1h[(long)n0 * F1 + col]       = __float2half_rn(lo);
        if (n0 + 1 < NN) g_xl1h[(long)(n0 + 1) * F1 + col] = __float2half_rn(hi);
    }
}

// attention dots for layer1: warp per node, vectorized half4 loads,
// 8-lane-group reduction (lanes 8h..8h+7 cover head h's 32 channels).
__global__ void __launch_bounds__(256) k_att1(const float* __restrict__ a1s,
                                              const float* __restrict__ a1d) {
    int n = blockIdx.x * 8 + (threadIdx.x >> 5);
    if (n >= NN) return;
    int l = threadIdx.x & 31;
    uint2 pv = *(const uint2*)(g_xl1h + (long)n * F1 + l * 4);
    float2 f0 = __half22float2(*reinterpret_cast<__half2*>(&pv.x));
    float2 f1 = __half22float2(*reinterpret_cast<__half2*>(&pv.y));
    float4 as = *(const float4*)&a1s[l * 4];
    float4 ad = *(const float4*)&a1d[l * 4];
    float vs = f0.x * as.x + f0.y * as.y + f1.x * as.z + f1.y * as.w;
    float vd = f0.x * ad.x + f0.y * ad.y + f1.x * ad.z + f1.y * ad.w;
    #pragma unroll
    for (int o = 4; o; o >>= 1) {
        vs += __shfl_xor_sync(0xffffffffu, vs, o);
        vd += __shfl_xor_sync(0xffffffffu, vd, o);
    }
    if ((l & 7) == 0) {
        int h = l >> 3;
        g_asrc1[n * HEADS + h] = vs;
        g_adst1[n * HEADS + h] = vd;
    }
}

// ---------------------------------------------------------------------------
// Edge-parallel ex for layer1: huge MLP, removes dependent loads from gather.
__global__ void __launch_bounds__(256) k_ex1() {
    int i = blockIdx.x * blockDim.x + threadIdx.x;
    if (i >= ETOT) return;
    int s = g_esrc[i], d = g_edst[i];
    float ea = g_eea[i];
    float4 as = *(const float4*)&g_asrc1[s * HEADS];
    float4 ad = *(const float4*)&g_adst1[d * HEADS];
    float4 cf = *(const float4*)g_coef1;
    float4 a;
    a.x = as.x + ad.x + ea * cf.x;
    a.y = as.y + ad.y + ea * cf.y;
    a.z = as.z + ad.z + ea * cf.z;
    a.w = as.w + ad.w + ea * cf.w;
    a.x = a.x > 0.f ? a.x : 0.2f * a.x;
    a.y = a.y > 0.f ? a.y : 0.2f * a.y;
    a.z = a.z > 0.f ? a.z : 0.2f * a.z;
    a.w = a.w > 0.f ? a.w : 0.2f * a.w;
    float4 e;
    e.x = __expf(a.x); e.y = __expf(a.y);
    e.z = __expf(a.z); e.w = __expf(a.w);
    g_ex1[i] = e;
}

// ---------------------------------------------------------------------------
// Gather edge pass layer1: warp per dst node. Loop body: one dependent level
// (s -> xl1h), unroll x2 for MLP=2. ex comes precomputed & sequential.
// Epilogue fuses normalize + bias1 + ELU -> g_h1.
__global__ void __launch_bounds__(256) k_edge1g(const float* __restrict__ bias1) {
    int d = blockIdx.x * 8 + (threadIdx.x >> 5);
    if (d >= NN) return;
    int l = threadIdx.x & 31;
    int h = l >> 3;
    int beg = g_off[d], end = g_off[d + 1];
    const float* exp_ = (const float*)g_ex1;   // scalar view, [j*4+h]
    float4 acc = make_float4(0.f, 0.f, 0.f, 0.f);
    float den = 0.f;
    int j = beg;
    for (; j + 2 <= end; j += 2) {
        int s0 = g_esrc[j], s1 = g_esrc[j + 1];
        uint2 p0 = *(const uint2*)(g_xl1h + (long)s0 * F1 + l * 4);
        uint2 p1 = *(const uint2*)(g_xl1h + (long)s1 * F1 + l * 4);
        float ex0 = exp_[j * 4 + h];
        float ex1v = exp_[(j + 1) * 4 + h];
        den += ex0 + ex1v;
        float2 a0 = __half22float2(*reinterpret_cast<__half2*>(&p0.x));
        float2 b0 = __half22float2(*reinterpret_cast<__half2*>(&p0.y));
        float2 a1 = __half22float2(*reinterpret_cast<__half2*>(&p1.x));
        float2 b1 = __half22float2(*reinterpret_cast<__half2*>(&p1.y));
        acc.x += ex0 * a0.x + ex1v * a1.x;
        acc.y += ex0 * a0.y + ex1v * a1.y;
        acc.z += ex0 * b0.x + ex1v * b1.x;
        acc.w += ex0 * b0.y + ex1v * b1.y;
    }
    if (j < end) {
        int s0 = g_esrc[j];
        uint2 p0 = *(const uint2*)(g_xl1h + (long)s0 * F1 + l * 4);
        float ex0 = exp_[j * 4 + h];
        den += ex0;
        float2 a0 = __half22float2(*reinterpret_cast<__half2*>(&p0.x));
        float2 b0 = __half22float2(*reinterpret_cast<__half2*>(&p0.y));
        acc.x += ex0 * a0.x; acc.y += ex0 * a0.y;
        acc.z += ex0 * b0.x; acc.w += ex0 * b0.y;
    }
    float inv = 1.f / den;
    float4 b = *(const float4*)&bias1[l * 4];
    float4 v;
    v.x = acc.x * inv + b.x; v.y = acc.y * inv + b.y;
    v.z = acc.z * inv + b.z; v.w = acc.w * inv + b.w;
    v.x = v.x > 0.f ? v.x : expm1f(v.x);
    v.y = v.y > 0.f ? v.y : expm1f(v.y);
    v.z = v.z > 0.f ? v.z : expm1f(v.z);
    v.w = v.w > 0.f ? v.w : expm1f(v.w);
    *(float4*)&g_h1[(long)d * F1 + l * 4] = v;
}

// ---------------------------------------------------------------------------
// xl2 = h1 @ W2 (128x32) + attention dots. Warp per node, W2 staged in smem.
__global__ void __launch_bounds__(256) k_lin2(
    const float* __restrict__ w2, const float* __restrict__ a2s,
    const float* __restrict__ a2d) {
    __shared__ float sw2[F1 * OUTC];
    for (int i = threadIdx.x; i < F1 * OUTC; i += 256) sw2[i] = w2[i];
    __syncthreads();
    int n = blockIdx.x * 8 + (threadIdx.x >> 5);
    if (n >= NN) return;
    int c = threadIdx.x & 31;

    float hreg[4];
    #pragma unroll
    for (int j = 0; j < 4; j++) hreg[j] = g_h1[(long)n * F1 + j * 32 + c];
    float acc = 0.f;
    #pragma unroll
    for (int j = 0; j < 4; j++) {
        #pragma unroll
        for (int kk = 0; kk < 32; kk++) {
            float hk = __shfl_sync(0xffffffffu, hreg[j], kk);
            acc += hk * sw2[(j * 32 + kk) * OUTC + c];
        }
    }
    g_xl2[n * OUTC + c] = acc;
    float vs = acc * a2s[c], vd = acc * a2d[c];
    for (int o = 16; o; o >>= 1) {
        vs += __shfl_xor_sync(0xffffffffu, vs, o);
        vd += __shfl_xor_sync(0xffffffffu, vd, o);
    }
    if (c == 0) { g_asrc2[n] = vs; g_adst2[n] = vd; }
}

// ---------------------------------------------------------------------------
__global__ void __launch_bounds__(256) k_ex2() {
    int i = blockIdx.x * blockDim.x + threadIdx.x;
    if (i >= ETOT) return;
    float alpha = g_asrc2[g_esrc[i]] + g_adst2[g_edst[i]] + g_eea[i] * g_coef2;
    alpha = alpha > 0.f ? alpha : 0.2f * alpha;
    g_ex2[i] = __expf(alpha);
}

// ---------------------------------------------------------------------------
// Gather edge pass layer2: warp per dst node; lane = out col; unroll x2.
__global__ void __launch_bounds__(256) k_edge2g(float* __restrict__ out,
                                                const float* __restrict__ bias2) {
    int d = blockIdx.x * 8 + (threadIdx.x >> 5);
    if (d >= NN) return;
    int l = threadIdx.x & 31;
    int beg = g_off[d], end = g_off[d + 1];
    float acc = 0.f, den = 0.f;
    int j = beg;
    for (; j + 2 <= end; j += 2) {
        int s0 = g_esrc[j], s1 = g_esrc[j + 1];
        float v0 = g_xl2[s0 * OUTC + l];
        float v1 = g_xl2[s1 * OUTC + l];
        float ex0 = g_ex2[j], ex1v = g_ex2[j + 1];
        den += ex0 + ex1v;
        acc += ex0 * v0 + ex1v * v1;
    }
    if (j < end) {
        int s0 = g_esrc[j];
        float ex0 = g_ex2[j];
        den += ex0;
        acc += ex0 * g_xl2[s0 * OUTC + l];
    }
    out[(long)d * OUTC + l] = acc / den + bias2[l];
}

// ---------------------------------------------------------------------------
extern "C" void kernel_launch(void* const* d_in, const int* in_sizes, int n_in,
                              void* d_out, int out_size) {
    const float* x        = (const float*)d_in[0];
    const int*   eidx     = (const int*)  d_in[1];
    const float* eattr    = (const float*)d_in[2];
    const float* lin1_w   = (const float*)d_in[3];
    const float* att1_src = (const float*)d_in[4];
    const float* att1_dst = (const float*)d_in[5];
    const float* lin1_ew  = (const float*)d_in[6];
    const float* att1_e   = (const float*)d_in[7];
    const float* bias1    = (const float*)d_in[8];
    const float* lin2_w   = (const float*)d_in[9];
    const float* att2_src = (const float*)d_in[10];
    const float* att2_dst = (const float*)d_in[11];
    const float* lin2_ew  = (const float*)d_in[12];
    const float* att2_e   = (const float*)d_in[13];
    const float* bias2    = (const float*)d_in[14];
    float* out = (float*)d_out;

    k_prep<<<512, 256>>>(eattr, lin1_ew, att1_e, lin2_ew, att2_e);
    k_hist<<<(ETOT + 255) / 256, 256>>>(eidx);
    k_scan<<<1, 1024>>>();
    k_scatter<<<(ETOT + 255) / 256, 256>>>(eidx, eattr);
    k_lin1<<<(NN + 31) / 32, 128>>>(x, lin1_w);
    k_att1<<<(NN + 7) / 8, 256>>>(att1_src, att1_dst);
    k_ex1<<<(ETOT + 255) / 256, 256>>>();
    k_edge1g<<<(NN + 7) / 8, 256>>>(bias1);
    k_lin2<<<(NN + 7) / 8, 256>>>(lin2_w, att2_src, att2_dst);
    k_ex2<<<(ETOT + 255) / 256, 256>>>();
    k_edge2g<<<(NN + 7) / 8, 256>>>(out, bias2);
}

// round 5
// speedup vs baseline: 1.9078x; 1.2055x over previous
#include <cuda_runtime.h>
#include <cuda_fp16.h>

#define NN 50000
#define EE 800000
#define ETOT (EE + NN)          // 850000
#define FIN 128
#define HID 32
#define HEADS 4
#define F1 128                  // HEADS*HID
#define OUTC 32

// ---- scratch (no allocs allowed) ----
__device__ __half g_xl1h[NN * F1];      // layer1 transformed features (fp16)
__device__ float g_h1[NN * F1];         // elu(normalized layer1 out + bias1)
__device__ __align__(16) float g_asrc1[NN * HEADS];
__device__ __align__(16) float g_adst1[NN * HEADS];
__device__ float g_xl2[NN * OUTC];
__device__ float g_asrc2[NN];
__device__ float g_adst2[NN];
__device__ float g_part[512];
__device__ float g_loopea;              // easum / EE
__device__ __align__(16) float g_coef1[4];
__device__ float g_coef2;
// CSR
__device__ int  g_cnt[NN];
__device__ int  g_off[NN + 1];
__device__ int  g_cur[NN];
__device__ int2 g_es[ETOT];             // dst-sorted (src, ea_bits)

#define FMA2(d, a, b) asm("fma.rn.f32x2 %0, %1, %2, %0;" : "+l"(d) : "l"(a), "l"(b))

// ---------------------------------------------------------------------------
// prep: zero cnt, easum partials, coef dots
__global__ void __launch_bounds__(256) k_prep(
    const float* __restrict__ ea,
    const float* __restrict__ l1e, const float* __restrict__ a1e,
    const float* __restrict__ l2e, const float* __restrict__ a2e) {
    int t0 = blockIdx.x * blockDim.x + threadIdx.x;
    int stride = gridDim.x * blockDim.x;
    for (int i = t0; i < NN; i += stride) g_cnt[i] = 0;

    float s = 0.f;
    for (int i = t0; i < EE; i += stride) s += ea[i];
    for (int o = 16; o; o >>= 1) s += __shfl_xor_sync(0xffffffffu, s, o);
    __shared__ float sh[8];
    if ((threadIdx.x & 31) == 0) sh[threadIdx.x >> 5] = s;
    __syncthreads();
    if (threadIdx.x < 8) {
        float v = sh[threadIdx.x];
        for (int o = 4; o; o >>= 1) v += __shfl_xor_sync(0xffu, v, o);
        if (threadIdx.x == 0) g_part[blockIdx.x] = v;
    }

    if (blockIdx.x == 0 && threadIdx.x < 128) {
        int t = threadIdx.x;
        float v = l1e[t] * a1e[t];
        for (int o = 16; o; o >>= 1) v += __shfl_xor_sync(0xffffffffu, v, o);
        if ((t & 31) == 0) g_coef1[t >> 5] = v;
        if (t < 32) {
            float v2 = l2e[t] * a2e[t];
            for (int o = 16; o; o >>= 1) v2 += __shfl_xor_sync(0xffffffffu, v2, o);
            if (t == 0) g_coef2 = v2;
        }
    }
}

// ---------------------------------------------------------------------------
__global__ void k_hist(const int* __restrict__ eidx) {
    int i = blockIdx.x * blockDim.x + threadIdx.x;
    if (i >= ETOT) return;
    int d = (i < EE) ? eidx[EE + i] : (i - EE);
    atomicAdd(&g_cnt[d], 1);
}

// ---------------------------------------------------------------------------
// single block: finalize easum + coalesced chunk-wise exclusive scan
__global__ void __launch_bounds__(1024) k_scan() {
    int t = threadIdx.x, lane = t & 31, w = t >> 5;

    __shared__ float esh[32];
    float ev = (t < 512) ? g_part[t] : 0.f;
    for (int o = 16; o; o >>= 1) ev += __shfl_xor_sync(0xffffffffu, ev, o);
    if (lane == 0) esh[w] = ev;
    __syncthreads();
    if (w == 0) {
        float v = esh[lane];
        for (int o = 16; o; o >>= 1) v += __shfl_xor_sync(0xffffffffu, v, o);
        if (lane == 0) g_loopea = v * (1.0f / EE);
    }

    __shared__ int wsum[32];
    __shared__ int s_carry;
    int running = 0;
    const int NCH = (NN + 1023) / 1024;   // 49
    for (int c = 0; c < NCH; c++) {
        int i = c * 1024 + t;
        int v = (i < NN) ? g_cnt[i] : 0;
        int inc = v;
        #pragma unroll
        for (int o = 1; o < 32; o <<= 1) {
            int u = __shfl_up_sync(0xffffffffu, inc, o);
            if (lane >= o) inc += u;
        }
        if (lane == 31) wsum[w] = inc;
        __syncthreads();
        if (w == 0) {
            int x0 = wsum[lane];
            int iv = x0;
            #pragma unroll
            for (int o = 1; o < 32; o <<= 1) {
                int u = __shfl_up_sync(0xffffffffu, iv, o);
                if (lane >= o) iv += u;
            }
            wsum[lane] = iv - x0;   // exclusive warp prefix
        }
        __syncthreads();
        int excl = running + wsum[w] + inc - v;
        if (i < NN) { g_off[i] = excl; g_cur[i] = excl; }
        if (t == 1023) s_carry = excl + v;
        __syncthreads();
        running = s_carry;
    }
    if (t == 0) g_off[NN] = ETOT;
}

// ---------------------------------------------------------------------------
__global__ void k_scatter(const int* __restrict__ eidx, const float* __restrict__ eattr) {
    int i = blockIdx.x * blockDim.x + threadIdx.x;
    if (i >= ETOT) return;
    int s, d; float ea;
    if (i < EE) { s = eidx[i]; d = eidx[EE + i]; ea = eattr[i]; }
    else        { s = i - EE;  d = s;            ea = g_loopea; }
    int pos = atomicAdd(&g_cur[d], 1);
    g_es[pos] = make_int2(s, __float_as_int(ea));
}

// ---------------------------------------------------------------------------
// xl1 = x @ W1 (128x128), f32x2 FMA, 32 nodes/block. Epilogue fuses the
// attention dots: warp wid == head wid, warp-reduce acc*a over 32 cols.
__global__ void __launch_bounds__(128) k_lin1(
    const float* __restrict__ x, const float* __restrict__ w,
    const float* __restrict__ a1s, const float* __restrict__ a1d) {
    __shared__ float sxT[FIN * 36];   // [k][node(+pad)]
    int t = threadIdx.x;
    int lane = t & 31, wid = t >> 5;
    int nbase = blockIdx.x * 32;

    #pragma unroll
    for (int jj = 0; jj < 8; jj++) {
        int j = wid * 8 + jj;
        int n = nbase + j;
        const float* xr = x + (long)min(n, NN - 1) * FIN;
        #pragma unroll
        for (int c = 0; c < 4; c++) {
            int k = c * 32 + lane;
            sxT[k * 36 + j] = (n < NN) ? xr[k] : 0.f;
        }
    }
    __syncthreads();

    unsigned long long acc[16];   // 16 x f32x2 = 32 node accumulators
    #pragma unroll
    for (int p = 0; p < 16; p++) acc[p] = 0ull;
    const int col = t;
    #pragma unroll 4
    for (int k = 0; k < FIN; k++) {
        float wv = w[k * F1 + col];
        unsigned long long wv2;
        asm("mov.b64 %0, {%1, %1};" : "=l"(wv2) : "f"(wv));
        #pragma unroll
        for (int jg = 0; jg < 8; jg++) {
            ulonglong2 xv = *(const ulonglong2*)&sxT[k * 36 + jg * 4];
            FMA2(acc[jg * 2 + 0], xv.x, wv2);
            FMA2(acc[jg * 2 + 1], xv.y, wv2);
        }
    }

    float sA = a1s[col], sD = a1d[col];
    #pragma unroll
    for (int p = 0; p < 16; p++) {
        float lo, hi;
        asm("mov.b64 {%0, %1}, %2;" : "=f"(lo), "=f"(hi) : "l"(acc[p]));
        int n0 = nbase + p * 2;
        if (n0 < NN)     g_xl1h[(long)n0 * F1 + col]       = __float2half_rn(lo);
        if (n0 + 1 < NN) g_xl1h[(long)(n0 + 1) * F1 + col] = __float2half_rn(hi);
        float vs0 = lo * sA, vd0 = lo * sD, vs1 = hi * sA, vd1 = hi * sD;
        #pragma unroll
        for (int o = 16; o; o >>= 1) {
            vs0 += __shfl_xor_sync(0xffffffffu, vs0, o);
            vd0 += __shfl_xor_sync(0xffffffffu, vd0, o);
            vs1 += __shfl_xor_sync(0xffffffffu, vs1, o);
            vd1 += __shfl_xor_sync(0xffffffffu, vd1, o);
        }
        if (lane == 0 && n0 < NN) {
            g_asrc1[n0 * HEADS + wid] = vs0;
            g_adst1[n0 * HEADS + wid] = vd0;
            if (n0 + 1 < NN) {
                g_asrc1[(n0 + 1) * HEADS + wid] = vs1;
                g_adst1[(n0 + 1) * HEADS + wid] = vd1;
            }
        }
    }
}

// ---------------------------------------------------------------------------
// Gather edge pass layer1 (alpha/exp fused in): warp per dst node.
// lane l -> head l/8, feature chunk [4l,4l+4). asrc1[s] and xl1h[s] loads
// both depend only on s -> issue in parallel. Unroll x2.
__global__ void __launch_bounds__(256) k_edge1g(const float* __restrict__ bias1) {
    int d = blockIdx.x * 8 + (threadIdx.x >> 5);
    if (d >= NN) return;
    int l = threadIdx.x & 31;
    int h = l >> 3;
    int beg = g_off[d], end = g_off[d + 1];
    float adst = g_adst1[d * HEADS + h];
    float cf = g_coef1[h];
    float4 acc = make_float4(0.f, 0.f, 0.f, 0.f);
    float den = 0.f;
    int j = beg;
    for (; j + 2 <= end; j += 2) {
        int2 e0 = g_es[j], e1 = g_es[j + 1];
        float as0 = g_asrc1[e0.x * HEADS + h];
        float as1 = g_asrc1[e1.x * HEADS + h];
        uint2 p0 = *(const uint2*)(g_xl1h + (long)e0.x * F1 + l * 4);
        uint2 p1 = *(const uint2*)(g_xl1h + (long)e1.x * F1 + l * 4);
        float al0 = as0 + adst + __int_as_float(e0.y) * cf;
        float al1 = as1 + adst + __int_as_float(e1.y) * cf;
        al0 = al0 > 0.f ? al0 : 0.2f * al0;
        al1 = al1 > 0.f ? al1 : 0.2f * al1;
        float ex0 = __expf(al0), ex1 = __expf(al1);
        den += ex0 + ex1;
        float2 a0 = __half22float2(*reinterpret_cast<__half2*>(&p0.x));
        float2 b0 = __half22float2(*reinterpret_cast<__half2*>(&p0.y));
        float2 a1 = __half22float2(*reinterpret_cast<__half2*>(&p1.x));
        float2 b1 = __half22float2(*reinterpret_cast<__half2*>(&p1.y));
        acc.x += ex0 * a0.x + ex1 * a1.x;
        acc.y += ex0 * a0.y + ex1 * a1.y;
        acc.z += ex0 * b0.x + ex1 * b1.x;
        acc.w += ex0 * b0.y + ex1 * b1.y;
    }
    if (j < end) {
        int2 e0 = g_es[j];
        float as0 = g_asrc1[e0.x * HEADS + h];
        uint2 p0 = *(const uint2*)(g_xl1h + (long)e0.x * F1 + l * 4);
        float al0 = as0 + adst + __int_as_float(e0.y) * cf;
        al0 = al0 > 0.f ? al0 : 0.2f * al0;
        float ex0 = __expf(al0);
        den += ex0;
        float2 a0 = __half22float2(*reinterpret_cast<__half2*>(&p0.x));
        float2 b0 = __half22float2(*reinterpret_cast<__half2*>(&p0.y));
        acc.x += ex0 * a0.x; acc.y += ex0 * a0.y;
        acc.z += ex0 * b0.x; acc.w += ex0 * b0.y;
    }
    float inv = 1.f / den;
    float4 b = *(const float4*)&bias1[l * 4];
    float4 v;
    v.x = acc.x * inv + b.x; v.y = acc.y * inv + b.y;
    v.z = acc.z * inv + b.z; v.w = acc.w * inv + b.w;
    v.x = v.x > 0.f ? v.x : expm1f(v.x);
    v.y = v.y > 0.f ? v.y : expm1f(v.y);
    v.z = v.z > 0.f ? v.z : expm1f(v.z);
    v.w = v.w > 0.f ? v.w : expm1f(v.w);
    *(float4*)&g_h1[(long)d * F1 + l * 4] = v;
}

// ---------------------------------------------------------------------------
// xl2 = h1 @ W2 (128x32) + attention dots. Warp per node, W2 staged in smem.
__global__ void __launch_bounds__(256) k_lin2(
    const float* __restrict__ w2, const float* __restrict__ a2s,
    const float* __restrict__ a2d) {
    __shared__ float sw2[F1 * OUTC];
    for (int i = threadIdx.x; i < F1 * OUTC; i += 256) sw2[i] = w2[i];
    __syncthreads();
    int n = blockIdx.x * 8 + (threadIdx.x >> 5);
    if (n >= NN) return;
    int c = threadIdx.x & 31;

    float hreg[4];
    #pragma unroll
    for (int j = 0; j < 4; j++) hreg[j] = g_h1[(long)n * F1 + j * 32 + c];
    float acc = 0.f;
    #pragma unroll
    for (int j = 0; j < 4; j++) {
        #pragma unroll
        for (int kk = 0; kk < 32; kk++) {
            float hk = __shfl_sync(0xffffffffu, hreg[j], kk);
            acc += hk * sw2[(j * 32 + kk) * OUTC + c];
        }
    }
    g_xl2[n * OUTC + c] = acc;
    float vs = acc * a2s[c], vd = acc * a2d[c];
    for (int o = 16; o; o >>= 1) {
        vs += __shfl_xor_sync(0xffffffffu, vs, o);
        vd += __shfl_xor_sync(0xffffffffu, vd, o);
    }
    if (c == 0) { g_asrc2[n] = vs; g_adst2[n] = vd; }
}

// ---------------------------------------------------------------------------
// Gather edge pass layer2 (alpha/exp fused): warp per dst node; lane = col.
__global__ void __launch_bounds__(256) k_edge2g(float* __restrict__ out,
                                                const float* __restrict__ bias2) {
    int d = blockIdx.x * 8 + (threadIdx.x >> 5);
    if (d >= NN) return;
    int l = threadIdx.x & 31;
    int beg = g_off[d], end = g_off[d + 1];
    float adst = g_adst2[d];
    float cf = g_coef2;
    float acc = 0.f, den = 0.f;
    int j = beg;
    for (; j + 2 <= end; j += 2) {
        int2 e0 = g_es[j], e1 = g_es[j + 1];
        float as0 = g_asrc2[e0.x];
        float as1 = g_asrc2[e1.x];
        float v0 = g_xl2[e0.x * OUTC + l];
        float v1 = g_xl2[e1.x * OUTC + l];
        float al0 = as0 + adst + __int_as_float(e0.y) * cf;
        float al1 = as1 + adst + __int_as_float(e1.y) * cf;
        al0 = al0 > 0.f ? al0 : 0.2f * al0;
        al1 = al1 > 0.f ? al1 : 0.2f * al1;
        float ex0 = __expf(al0), ex1 = __expf(al1);
        den += ex0 + ex1;
        acc += ex0 * v0 + ex1 * v1;
    }
    if (j < end) {
        int2 e0 = g_es[j];
        float al0 = g_asrc2[e0.x] + adst + __int_as_float(e0.y) * cf;
        al0 = al0 > 0.f ? al0 : 0.2f * al0;
        float ex0 = __expf(al0);
        den += ex0;
        acc += ex0 * g_xl2[e0.x * OUTC + l];
    }
    out[(long)d * OUTC + l] = acc / den + bias2[l];
}

// ---------------------------------------------------------------------------
extern "C" void kernel_launch(void* const* d_in, const int* in_sizes, int n_in,
                              void* d_out, int out_size) {
    const float* x        = (const float*)d_in[0];
    const int*   eidx     = (const int*)  d_in[1];
    const float* eattr    = (const float*)d_in[2];
    const float* lin1_w   = (const float*)d_in[3];
    const float* att1_src = (const float*)d_in[4];
    const float* att1_dst = (const float*)d_in[5];
    const float* lin1_ew  = (const float*)d_in[6];
    const float* att1_e   = (const float*)d_in[7];
    const float* bias1    = (const float*)d_in[8];
    const float* lin2_w   = (const float*)d_in[9];
    const float* att2_src = (const float*)d_in[10];
    const float* att2_dst = (const float*)d_in[11];
    const float* lin2_ew  = (const float*)d_in[12];
    const float* att2_e   = (const float*)d_in[13];
    const float* bias2    = (const float*)d_in[14];
    float* out = (float*)d_out;

    // lazily-created side stream + events (created on first, uncaptured call;
    // no device memory involved)
    static cudaStream_t sB = nullptr;
    static cudaEvent_t evFork = nullptr, evB = nullptr;
    if (sB == nullptr) {
        cudaStreamCreateWithFlags(&sB, cudaStreamNonBlocking);
        cudaEventCreateWithFlags(&evFork, cudaEventDisableTiming);
        cudaEventCreateWithFlags(&evB, cudaEventDisableTiming);
    }

    // fork: lin1 (independent of CSR build) runs on sB
    cudaEventRecord(evFork, 0);
    cudaStreamWaitEvent(sB, evFork, 0);
    k_lin1<<<(NN + 31) / 32, 128, 0, sB>>>(x, lin1_w, att1_src, att1_dst);
    cudaEventRecord(evB, sB);

    // CSR build chain on the main stream
    k_prep<<<512, 256>>>(eattr, lin1_ew, att1_e, lin2_ew, att2_e);
    k_hist<<<(ETOT + 255) / 256, 256>>>(eidx);
    k_scan<<<1, 1024>>>();
    k_scatter<<<(ETOT + 255) / 256, 256>>>(eidx, eattr);

    // join lin1 before the gather
    cudaStreamWaitEvent(0, evB, 0);
    k_edge1g<<<(NN + 7) / 8, 256>>>(bias1);
    k_lin2<<<(NN + 7) / 8, 256>>>(lin2_w, att2_src, att2_dst);
    k_edge2g<<<(NN + 7) / 8, 256>>>(out, bias2);
}

// round 6
// speedup vs baseline: 2.2095x; 1.1582x over previous
#include <cuda_runtime.h>
#include <cuda_fp16.h>

#define NN 50000
#define EE 800000
#define ETOT (EE + NN)          // 850000
#define FIN 128
#define HID 32
#define HEADS 4
#define F1 128                  // HEADS*HID
#define OUTC 32
#define SCAN_B 49               // ceil(NN/1024)

// ---- scratch (no allocs allowed) ----
__device__ __half g_xl1h[NN * F1];      // layer1 transformed features (fp16)
__device__ float g_h1[NN * F1];         // elu(normalized layer1 out + bias1)
__device__ __align__(16) float g_asrc1[NN * HEADS];
__device__ __align__(16) float g_adst1[NN * HEADS];
__device__ float g_xl2[NN * OUTC];
__device__ float g_asrc2[NN];
__device__ float g_adst2[NN];
__device__ float g_part[512];
__device__ float g_loopea;              // easum / EE
__device__ __align__(16) float g_coef1[4];
__device__ float g_coef2;
// CSR
__device__ int  g_cnt[NN];
__device__ int  g_bsum[SCAN_B];
__device__ int  g_bpre[SCAN_B];
__device__ int  g_off[NN + 1];
__device__ int  g_cur[NN];
__device__ int2 g_es[ETOT];             // dst-sorted (src, ea_bits)

#define FMA2(d, a, b) asm("fma.rn.f32x2 %0, %1, %2, %0;" : "+l"(d) : "l"(a), "l"(b))

// ---------------------------------------------------------------------------
// zero counts (main-stream prefix for hist)
__global__ void __launch_bounds__(256) k_zero() {
    int i = blockIdx.x * blockDim.x + threadIdx.x;
    if (i < NN) g_cnt[i] = 0;
}

// easum partials + coef dots (side stream, overlapped)
__global__ void __launch_bounds__(256) k_prepmisc(
    const float* __restrict__ ea,
    const float* __restrict__ l1e, const float* __restrict__ a1e,
    const float* __restrict__ l2e, const float* __restrict__ a2e) {
    int t0 = blockIdx.x * blockDim.x + threadIdx.x;
    int stride = gridDim.x * blockDim.x;
    float s = 0.f;
    for (int i = t0; i < EE; i += stride) s += ea[i];
    for (int o = 16; o; o >>= 1) s += __shfl_xor_sync(0xffffffffu, s, o);
    __shared__ float sh[8];
    if ((threadIdx.x & 31) == 0) sh[threadIdx.x >> 5] = s;
    __syncthreads();
    if (threadIdx.x < 8) {
        float v = sh[threadIdx.x];
        for (int o = 4; o; o >>= 1) v += __shfl_xor_sync(0xffu, v, o);
        if (threadIdx.x == 0) g_part[blockIdx.x] = v;
    }
    if (blockIdx.x == 0 && threadIdx.x < 128) {
        int t = threadIdx.x;
        float v = l1e[t] * a1e[t];
        for (int o = 16; o; o >>= 1) v += __shfl_xor_sync(0xffffffffu, v, o);
        if ((t & 31) == 0) g_coef1[t >> 5] = v;
        if (t < 32) {
            float v2 = l2e[t] * a2e[t];
            for (int o = 16; o; o >>= 1) v2 += __shfl_xor_sync(0xffffffffu, v2, o);
            if (t == 0) g_coef2 = v2;
        }
    }
}

// ---------------------------------------------------------------------------
__global__ void k_hist(const int* __restrict__ eidx) {
    int i = blockIdx.x * blockDim.x + threadIdx.x;
    if (i >= ETOT) return;
    int d = (i < EE) ? eidx[EE + i] : (i - EE);
    atomicAdd(&g_cnt[d], 1);
}

// ---------------------------------------------------------------------------
// scan phase A: per-block reduce of 1024-chunk
__global__ void __launch_bounds__(1024) k_scanA() {
    int t = threadIdx.x, lane = t & 31, w = t >> 5;
    int i = blockIdx.x * 1024 + t;
    int v = (i < NN) ? g_cnt[i] : 0;
    for (int o = 16; o; o >>= 1) v += __shfl_xor_sync(0xffffffffu, v, o);
    __shared__ int sh[32];
    if (lane == 0) sh[w] = v;
    __syncthreads();
    if (w == 0) {
        int u = sh[lane];
        for (int o = 16; o; o >>= 1) u += __shfl_xor_sync(0xffffffffu, u, o);
        if (lane == 0) g_bsum[blockIdx.x] = u;
    }
}

// scan phase B: scan 49 block sums + finalize easum. 1 block, 512 threads.
__global__ void __launch_bounds__(512) k_scanB() {
    int t = threadIdx.x, lane = t & 31, w = t >> 5;
    // easum finalize
    __shared__ float esh[16];
    float ev = g_part[t];
    for (int o = 16; o; o >>= 1) ev += __shfl_xor_sync(0xffffffffu, ev, o);
    if (lane == 0) esh[w] = ev;
    __syncthreads();
    if (t < 16) {
        float v = esh[t];
        for (int o = 8; o; o >>= 1) v += __shfl_xor_sync(0xffffu, v, o);
        if (t == 0) g_loopea = v * (1.0f / EE);
    }
    // scan of g_bsum (49 <= 64): Hillis-Steele in shared
    __shared__ int arr[64];
    if (t < 64) arr[t] = (t < SCAN_B) ? g_bsum[t] : 0;
    __syncthreads();
    #pragma unroll
    for (int o = 1; o < 64; o <<= 1) {
        int v = 0;
        if (t < 64 && t >= o) v = arr[t - o];
        __syncthreads();
        if (t < 64) arr[t] += v;
        __syncthreads();
    }
    if (t < SCAN_B) g_bpre[t] = arr[t] - g_bsum[t];   // exclusive
}

// scan phase C: block-local exclusive scan + block offset -> g_off/g_cur
__global__ void __launch_bounds__(1024) k_scanC() {
    int t = threadIdx.x, lane = t & 31, w = t >> 5;
    int i = blockIdx.x * 1024 + t;
    int v = (i < NN) ? g_cnt[i] : 0;
    int inc = v;
    #pragma unroll
    for (int o = 1; o < 32; o <<= 1) {
        int u = __shfl_up_sync(0xffffffffu, inc, o);
        if (lane >= o) inc += u;
    }
    __shared__ int wsum[32];
    if (lane == 31) wsum[w] = inc;
    __syncthreads();
    if (w == 0) {
        int x0 = wsum[lane];
        int iv = x0;
        #pragma unroll
        for (int o = 1; o < 32; o <<= 1) {
            int u = __shfl_up_sync(0xffffffffu, iv, o);
            if (lane >= o) iv += u;
        }
        wsum[lane] = iv - x0;
    }
    __syncthreads();
    int excl = g_bpre[blockIdx.x] + wsum[w] + inc - v;
    if (i <= NN) g_off[i] = excl;   // i==NN lands on total == ETOT
    if (i < NN)  g_cur[i] = excl;
}

// ---------------------------------------------------------------------------
__global__ void k_scatter(const int* __restrict__ eidx, const float* __restrict__ eattr) {
    int i = blockIdx.x * blockDim.x + threadIdx.x;
    if (i >= ETOT) return;
    int s, d; float ea;
    if (i < EE) { s = eidx[i]; d = eidx[EE + i]; ea = eattr[i]; }
    else        { s = i - EE;  d = s;            ea = g_loopea; }
    int pos = atomicAdd(&g_cur[d], 1);
    g_es[pos] = make_int2(s, __float_as_int(ea));
}

// ---------------------------------------------------------------------------
// xl1 = x @ W1 (128x128), f32x2 FMA, 32 nodes/block, fused attention dots.
__global__ void __launch_bounds__(128) k_lin1(
    const float* __restrict__ x, const float* __restrict__ w,
    const float* __restrict__ a1s, const float* __restrict__ a1d) {
    __shared__ float sxT[FIN * 36];   // [k][node(+pad)]
    int t = threadIdx.x;
    int lane = t & 31, wid = t >> 5;
    int nbase = blockIdx.x * 32;

    #pragma unroll
    for (int jj = 0; jj < 8; jj++) {
        int j = wid * 8 + jj;
        int n = nbase + j;
        const float* xr = x + (long)min(n, NN - 1) * FIN;
        #pragma unroll
        for (int c = 0; c < 4; c++) {
            int k = c * 32 + lane;
            sxT[k * 36 + j] = (n < NN) ? xr[k] : 0.f;
        }
    }
    __syncthreads();

    unsigned long long acc[16];
    #pragma unroll
    for (int p = 0; p < 16; p++) acc[p] = 0ull;
    const int col = t;
    #pragma unroll 4
    for (int k = 0; k < FIN; k++) {
        float wv = w[k * F1 + col];
        unsigned long long wv2;
        asm("mov.b64 %0, {%1, %1};" : "=l"(wv2) : "f"(wv));
        #pragma unroll
        for (int jg = 0; jg < 8; jg++) {
            ulonglong2 xv = *(const ulonglong2*)&sxT[k * 36 + jg * 4];
            FMA2(acc[jg * 2 + 0], xv.x, wv2);
            FMA2(acc[jg * 2 + 1], xv.y, wv2);
        }
    }

    float sA = a1s[col], sD = a1d[col];
    #pragma unroll
    for (int p = 0; p < 16; p++) {
        float lo, hi;
        asm("mov.b64 {%0, %1}, %2;" : "=f"(lo), "=f"(hi) : "l"(acc[p]));
        int n0 = nbase + p * 2;
        if (n0 < NN)     g_xl1h[(long)n0 * F1 + col]       = __float2half_rn(lo);
        if (n0 + 1 < NN) g_xl1h[(long)(n0 + 1) * F1 + col] = __float2half_rn(hi);
        float vs0 = lo * sA, vd0 = lo * sD, vs1 = hi * sA, vd1 = hi * sD;
        #pragma unroll
        for (int o = 16; o; o >>= 1) {
            vs0 += __shfl_xor_sync(0xffffffffu, vs0, o);
            vd0 += __shfl_xor_sync(0xffffffffu, vd0, o);
            vs1 += __shfl_xor_sync(0xffffffffu, vs1, o);
            vd1 += __shfl_xor_sync(0xffffffffu, vd1, o);
        }
        if (lane == 0 && n0 < NN) {
            g_asrc1[n0 * HEADS + wid] = vs0;
            g_adst1[n0 * HEADS + wid] = vd0;
            if (n0 + 1 < NN) {
                g_asrc1[(n0 + 1) * HEADS + wid] = vs1;
                g_adst1[(n0 + 1) * HEADS + wid] = vd1;
            }
        }
    }
}

// ---------------------------------------------------------------------------
// Gather edge pass layer1: warp per dst node, fused alpha/exp, unroll x2.
__global__ void __launch_bounds__(256) k_edge1g(const float* __restrict__ bias1) {
    int d = blockIdx.x * 8 + (threadIdx.x >> 5);
    if (d >= NN) return;
    int l = threadIdx.x & 31;
    int h = l >> 3;
    int beg = g_off[d], end = g_off[d + 1];
    float adst = g_adst1[d * HEADS + h];
    float cf = g_coef1[h];
    float4 acc = make_float4(0.f, 0.f, 0.f, 0.f);
    float den = 0.f;
    int j = beg;
    for (; j + 2 <= end; j += 2) {
        int2 e0 = g_es[j], e1 = g_es[j + 1];
        float as0 = g_asrc1[e0.x * HEADS + h];
        float as1 = g_asrc1[e1.x * HEADS + h];
        uint2 p0 = *(const uint2*)(g_xl1h + (long)e0.x * F1 + l * 4);
        uint2 p1 = *(const uint2*)(g_xl1h + (long)e1.x * F1 + l * 4);
        float al0 = as0 + adst + __int_as_float(e0.y) * cf;
        float al1 = as1 + adst + __int_as_float(e1.y) * cf;
        al0 = al0 > 0.f ? al0 : 0.2f * al0;
        al1 = al1 > 0.f ? al1 : 0.2f * al1;
        float ex0 = __expf(al0), ex1 = __expf(al1);
        den += ex0 + ex1;
        float2 a0 = __half22float2(*reinterpret_cast<__half2*>(&p0.x));
        float2 b0 = __half22float2(*reinterpret_cast<__half2*>(&p0.y));
        float2 a1 = __half22float2(*reinterpret_cast<__half2*>(&p1.x));
        float2 b1 = __half22float2(*reinterpret_cast<__half2*>(&p1.y));
        acc.x += ex0 * a0.x + ex1 * a1.x;
        acc.y += ex0 * a0.y + ex1 * a1.y;
        acc.z += ex0 * b0.x + ex1 * b1.x;
        acc.w += ex0 * b0.y + ex1 * b1.y;
    }
    if (j < end) {
        int2 e0 = g_es[j];
        float as0 = g_asrc1[e0.x * HEADS + h];
        uint2 p0 = *(const uint2*)(g_xl1h + (long)e0.x * F1 + l * 4);
        float al0 = as0 + adst + __int_as_float(e0.y) * cf;
        al0 = al0 > 0.f ? al0 : 0.2f * al0;
        float ex0 = __expf(al0);
        den += ex0;
        float2 a0 = __half22float2(*reinterpret_cast<__half2*>(&p0.x));
        float2 b0 = __half22float2(*reinterpret_cast<__half2*>(&p0.y));
        acc.x += ex0 * a0.x; acc.y += ex0 * a0.y;
        acc.z += ex0 * b0.x; acc.w += ex0 * b0.y;
    }
    float inv = 1.f / den;
    float4 b = *(const float4*)&bias1[l * 4];
    float4 v;
    v.x = acc.x * inv + b.x; v.y = acc.y * inv + b.y;
    v.z = acc.z * inv + b.z; v.w = acc.w * inv + b.w;
    v.x = v.x > 0.f ? v.x : expm1f(v.x);
    v.y = v.y > 0.f ? v.y : expm1f(v.y);
    v.z = v.z > 0.f ? v.z : expm1f(v.z);
    v.w = v.w > 0.f ? v.w : expm1f(v.w);
    *(float4*)&g_h1[(long)d * F1 + l * 4] = v;
}

// ---------------------------------------------------------------------------
// xl2 = h1 @ W2 (128x32) + attention dots. Warp per node, W2 staged in smem.
__global__ void __launch_bounds__(256) k_lin2(
    const float* __restrict__ w2, const float* __restrict__ a2s,
    const float* __restrict__ a2d) {
    __shared__ float sw2[F1 * OUTC];
    for (int i = threadIdx.x; i < F1 * OUTC; i += 256) sw2[i] = w2[i];
    __syncthreads();
    int n = blockIdx.x * 8 + (threadIdx.x >> 5);
    if (n >= NN) return;
    int c = threadIdx.x & 31;

    float hreg[4];
    #pragma unroll
    for (int j = 0; j < 4; j++) hreg[j] = g_h1[(long)n * F1 + j * 32 + c];
    float acc = 0.f;
    #pragma unroll
    for (int j = 0; j < 4; j++) {
        #pragma unroll
        for (int kk = 0; kk < 32; kk++) {
            float hk = __shfl_sync(0xffffffffu, hreg[j], kk);
            acc += hk * sw2[(j * 32 + kk) * OUTC + c];
        }
    }
    g_xl2[n * OUTC + c] = acc;
    float vs = acc * a2s[c], vd = acc * a2d[c];
    for (int o = 16; o; o >>= 1) {
        vs += __shfl_xor_sync(0xffffffffu, vs, o);
        vd += __shfl_xor_sync(0xffffffffu, vd, o);
    }
    if (c == 0) { g_asrc2[n] = vs; g_adst2[n] = vd; }
}

// ---------------------------------------------------------------------------
// Gather edge pass layer2: warp per dst node; lane = out col.
__global__ void __launch_bounds__(256) k_edge2g(float* __restrict__ out,
                                                const float* __restrict__ bias2) {
    int d = blockIdx.x * 8 + (threadIdx.x >> 5);
    if (d >= NN) return;
    int l = threadIdx.x & 31;
    int beg = g_off[d], end = g_off[d + 1];
    float adst = g_adst2[d];
    float cf = g_coef2;
    float acc = 0.f, den = 0.f;
    int j = beg;
    for (; j + 2 <= end; j += 2) {
        int2 e0 = g_es[j], e1 = g_es[j + 1];
        float as0 = g_asrc2[e0.x];
        float as1 = g_asrc2[e1.x];
        float v0 = g_xl2[e0.x * OUTC + l];
        float v1 = g_xl2[e1.x * OUTC + l];
        float al0 = as0 + adst + __int_as_float(e0.y) * cf;
        float al1 = as1 + adst + __int_as_float(e1.y) * cf;
        al0 = al0 > 0.f ? al0 : 0.2f * al0;
        al1 = al1 > 0.f ? al1 : 0.2f * al1;
        float ex0 = __expf(al0), ex1 = __expf(al1);
        den += ex0 + ex1;
        acc += ex0 * v0 + ex1 * v1;
    }
    if (j < end) {
        int2 e0 = g_es[j];
        float al0 = g_asrc2[e0.x] + adst + __int_as_float(e0.y) * cf;
        al0 = al0 > 0.f ? al0 : 0.2f * al0;
        float ex0 = __expf(al0);
        den += ex0;
        acc += ex0 * g_xl2[e0.x * OUTC + l];
    }
    out[(long)d * OUTC + l] = acc / den + bias2[l];
}

// ---------------------------------------------------------------------------
extern "C" void kernel_launch(void* const* d_in, const int* in_sizes, int n_in,
                              void* d_out, int out_size) {
    const float* x        = (const float*)d_in[0];
    const int*   eidx     = (const int*)  d_in[1];
    const float* eattr    = (const float*)d_in[2];
    const float* lin1_w   = (const float*)d_in[3];
    const float* att1_src = (const float*)d_in[4];
    const float* att1_dst = (const float*)d_in[5];
    const float* lin1_ew  = (const float*)d_in[6];
    const float* att1_e   = (const float*)d_in[7];
    const float* bias1    = (const float*)d_in[8];
    const float* lin2_w   = (const float*)d_in[9];
    const float* att2_src = (const float*)d_in[10];
    const float* att2_dst = (const float*)d_in[11];
    const float* lin2_ew  = (const float*)d_in[12];
    const float* att2_e   = (const float*)d_in[13];
    const float* bias2    = (const float*)d_in[14];
    float* out = (float*)d_out;

    static cudaStream_t sB = nullptr;
    static cudaEvent_t evFork = nullptr, evMisc = nullptr, evB = nullptr;
    if (sB == nullptr) {
        cudaStreamCreateWithFlags(&sB, cudaStreamNonBlocking);
        cudaEventCreateWithFlags(&evFork, cudaEventDisableTiming);
        cudaEventCreateWithFlags(&evMisc, cudaEventDisableTiming);
        cudaEventCreateWithFlags(&evB, cudaEventDisableTiming);
    }

    // fork side stream: easum/coef partials, then lin1 (both independent of CSR)
    cudaEventRecord(evFork, 0);
    cudaStreamWaitEvent(sB, evFork, 0);
    k_prepmisc<<<512, 256, 0, sB>>>(eattr, lin1_ew, att1_e, lin2_ew, att2_e);
    cudaEventRecord(evMisc, sB);
    k_lin1<<<(NN + 31) / 32, 128, 0, sB>>>(x, lin1_w, att1_src, att1_dst);
    cudaEventRecord(evB, sB);

    // CSR build chain on the main stream
    k_zero<<<(NN + 255) / 256, 256>>>();
    k_hist<<<(ETOT + 255) / 256, 256>>>(eidx);
    k_scanA<<<SCAN_B, 1024>>>();
    cudaStreamWaitEvent(0, evMisc, 0);   // g_part ready for easum finalize
    k_scanB<<<1, 512>>>();
    k_scanC<<<SCAN_B, 1024>>>();
    k_scatter<<<(ETOT + 255) / 256, 256>>>(eidx, eattr);

    // join lin1 before the gather
    cudaStreamWaitEvent(0, evB, 0);
    k_edge1g<<<(NN + 7) / 8, 256>>>(bias1);
    k_lin2<<<(NN + 7) / 8, 256>>>(lin2_w, att2_src, att2_dst);
    k_edge2g<<<(NN + 7) / 8, 256>>>(out, bias2);
}

// round 8
// speedup vs baseline: 2.4992x; 1.1311x over previous
#include <cuda_runtime.h>
#include <cuda_fp16.h>

#define NN 50000
#define EE 800000
#define ETOT (EE + NN)          // 850000
#define FIN 128
#define HID 32
#define HEADS 4
#define F1 128                  // HEADS*HID
#define OUTC 32
#define SCAN_B 49               // ceil(NN/1024)

// ---- scratch (no allocs allowed) ----
__device__ __half g_xl1h[NN * F1];      // layer1 transformed features (fp16)
__device__ __align__(16) float g_asrc1[NN * HEADS];
__device__ __align__(16) float g_adst1[NN * HEADS];
__device__ float g_xl2[NN * OUTC];
__device__ float g_asrc2[NN];
__device__ float g_adst2[NN];
__device__ float g_part[512];
__device__ float g_loopea;              // easum / EE
__device__ __align__(16) float g_coef1[4];
__device__ float g_coef2;
// CSR
__device__ int  g_cnt[NN];
__device__ int  g_bsum[SCAN_B];
__device__ int  g_bpre[SCAN_B];
__device__ int  g_off[NN + 1];
__device__ int  g_cur[NN];
__device__ int2 g_es[ETOT];             // dst-sorted (src, ea_bits)

#define FMA2(d, a, b) asm("fma.rn.f32x2 %0, %1, %2, %0;" : "+l"(d) : "l"(a), "l"(b))

// ---------------------------------------------------------------------------
__global__ void __launch_bounds__(256) k_zero() {
    int i = blockIdx.x * blockDim.x + threadIdx.x;
    if (i < NN) g_cnt[i] = 0;
}

// easum partials + coef dots (side stream, overlapped)
__global__ void __launch_bounds__(256) k_prepmisc(
    const float* __restrict__ ea,
    const float* __restrict__ l1e, const float* __restrict__ a1e,
    const float* __restrict__ l2e, const float* __restrict__ a2e) {
    int t0 = blockIdx.x * blockDim.x + threadIdx.x;
    int stride = gridDim.x * blockDim.x;
    float s = 0.f;
    for (int i = t0; i < EE; i += stride) s += ea[i];
    for (int o = 16; o; o >>= 1) s += __shfl_xor_sync(0xffffffffu, s, o);
    __shared__ float sh[8];
    if ((threadIdx.x & 31) == 0) sh[threadIdx.x >> 5] = s;
    __syncthreads();
    if (threadIdx.x < 8) {
        float v = sh[threadIdx.x];
        for (int o = 4; o; o >>= 1) v += __shfl_xor_sync(0xffu, v, o);
        if (threadIdx.x == 0) g_part[blockIdx.x] = v;
    }
    if (blockIdx.x == 0 && threadIdx.x < 128) {
        int t = threadIdx.x;
        float v = l1e[t] * a1e[t];
        for (int o = 16; o; o >>= 1) v += __shfl_xor_sync(0xffffffffu, v, o);
        if ((t & 31) == 0) g_coef1[t >> 5] = v;
        if (t < 32) {
            float v2 = l2e[t] * a2e[t];
            for (int o = 16; o; o >>= 1) v2 += __shfl_xor_sync(0xffffffffu, v2, o);
            if (t == 0) g_coef2 = v2;
        }
    }
}

// ---------------------------------------------------------------------------
// hist: 4 edges/thread, int4 fast path, 4 independent atomic chains
__global__ void __launch_bounds__(256) k_hist(const int* __restrict__ eidx) {
    int i0 = (blockIdx.x * blockDim.x + threadIdx.x) * 4;
    if (i0 >= ETOT) return;
    if (i0 + 3 < EE) {
        int4 dv = *(const int4*)&eidx[EE + i0];
        atomicAdd(&g_cnt[dv.x], 1);
        atomicAdd(&g_cnt[dv.y], 1);
        atomicAdd(&g_cnt[dv.z], 1);
        atomicAdd(&g_cnt[dv.w], 1);
    } else {
        #pragma unroll 1
        for (int q = 0; q < 4; q++) {
            int i = i0 + q;
            if (i >= ETOT) break;
            int d = (i < EE) ? eidx[EE + i] : (i - EE);
            atomicAdd(&g_cnt[d], 1);
        }
    }
}

// ---------------------------------------------------------------------------
__global__ void __launch_bounds__(1024) k_scanA() {
    int t = threadIdx.x, lane = t & 31, w = t >> 5;
    int i = blockIdx.x * 1024 + t;
    int v = (i < NN) ? g_cnt[i] : 0;
    for (int o = 16; o; o >>= 1) v += __shfl_xor_sync(0xffffffffu, v, o);
    __shared__ int sh[32];
    if (lane == 0) sh[w] = v;
    __syncthreads();
    if (w == 0) {
        int u = sh[lane];
        for (int o = 16; o; o >>= 1) u += __shfl_xor_sync(0xffffffffu, u, o);
        if (lane == 0) g_bsum[blockIdx.x] = u;
    }
}

__global__ void __launch_bounds__(512) k_scanB() {
    int t = threadIdx.x, lane = t & 31, w = t >> 5;
    __shared__ float esh[16];
    float ev = g_part[t];
    for (int o = 16; o; o >>= 1) ev += __shfl_xor_sync(0xffffffffu, ev, o);
    if (lane == 0) esh[w] = ev;
    __syncthreads();
    if (t < 16) {
        float v = esh[t];
        for (int o = 8; o; o >>= 1) v += __shfl_xor_sync(0xffffu, v, o);
        if (t == 0) g_loopea = v * (1.0f / EE);
    }
    __shared__ int arr[64];
    if (t < 64) arr[t] = (t < SCAN_B) ? g_bsum[t] : 0;
    __syncthreads();
    #pragma unroll
    for (int o = 1; o < 64; o <<= 1) {
        int v = 0;
        if (t < 64 && t >= o) v = arr[t - o];
        __syncthreads();
        if (t < 64) arr[t] += v;
        __syncthreads();
    }
    if (t < SCAN_B) g_bpre[t] = arr[t] - g_bsum[t];
}

__global__ void __launch_bounds__(1024) k_scanC() {
    int t = threadIdx.x, lane = t & 31, w = t >> 5;
    int i = blockIdx.x * 1024 + t;
    int v = (i < NN) ? g_cnt[i] : 0;
    int inc = v;
    #pragma unroll
    for (int o = 1; o < 32; o <<= 1) {
        int u = __shfl_up_sync(0xffffffffu, inc, o);
        if (lane >= o) inc += u;
    }
    __shared__ int wsum[32];
    if (lane == 31) wsum[w] = inc;
    __syncthreads();
    if (w == 0) {
        int x0 = wsum[lane];
        int iv = x0;
        #pragma unroll
        for (int o = 1; o < 32; o <<= 1) {
            int u = __shfl_up_sync(0xffffffffu, iv, o);
            if (lane >= o) iv += u;
        }
        wsum[lane] = iv - x0;
    }
    __syncthreads();
    int excl = g_bpre[blockIdx.x] + wsum[w] + inc - v;
    if (i <= NN) g_off[i] = excl;
    if (i < NN)  g_cur[i] = excl;
}

// ---------------------------------------------------------------------------
// scatter: 4 edges/thread, int4 fast path
__global__ void __launch_bounds__(256) k_scatter(const int* __restrict__ eidx,
                                                 const float* __restrict__ eattr) {
    int i0 = (blockIdx.x * blockDim.x + threadIdx.x) * 4;
    if (i0 >= ETOT) return;
    if (i0 + 3 < EE) {
        int4 sv = *(const int4*)&eidx[i0];
        int4 dv = *(const int4*)&eidx[EE + i0];
        float4 av = *(const float4*)&eattr[i0];
        int p0 = atomicAdd(&g_cur[dv.x], 1);
        int p1 = atomicAdd(&g_cur[dv.y], 1);
        int p2 = atomicAdd(&g_cur[dv.z], 1);
        int p3 = atomicAdd(&g_cur[dv.w], 1);
        g_es[p0] = make_int2(sv.x, __float_as_int(av.x));
        g_es[p1] = make_int2(sv.y, __float_as_int(av.y));
        g_es[p2] = make_int2(sv.z, __float_as_int(av.z));
        g_es[p3] = make_int2(sv.w, __float_as_int(av.w));
    } else {
        #pragma unroll 1
        for (int q = 0; q < 4; q++) {
            int i = i0 + q;
            if (i >= ETOT) break;
            int s, d; float ea;
            if (i < EE) { s = eidx[i]; d = eidx[EE + i]; ea = eattr[i]; }
            else        { s = i - EE;  d = s;            ea = g_loopea; }
            int pos = atomicAdd(&g_cur[d], 1);
            g_es[pos] = make_int2(s, __float_as_int(ea));
        }
    }
}

// ---------------------------------------------------------------------------
// xl1 = x @ W1 (128x128), f32x2 FMA, 32 nodes/block, fused attention dots.
__global__ void __launch_bounds__(128) k_lin1(
    const float* __restrict__ x, const float* __restrict__ w,
    const float* __restrict__ a1s, const float* __restrict__ a1d) {
    __shared__ float sxT[FIN * 36];
    int t = threadIdx.x;
    int lane = t & 31, wid = t >> 5;
    int nbase = blockIdx.x * 32;

    #pragma unroll
    for (int jj = 0; jj < 8; jj++) {
        int j = wid * 8 + jj;
        int n = nbase + j;
        const float* xr = x + (long)min(n, NN - 1) * FIN;
        #pragma unroll
        for (int c = 0; c < 4; c++) {
            int k = c * 32 + lane;
            sxT[k * 36 + j] = (n < NN) ? xr[k] : 0.f;
        }
    }
    __syncthreads();

    unsigned long long acc[16];
    #pragma unroll
    for (int p = 0; p < 16; p++) acc[p] = 0ull;
    const int col = t;
    #pragma unroll 4
    for (int k = 0; k < FIN; k++) {
        float wv = w[k * F1 + col];
        unsigned long long wv2;
        asm("mov.b64 %0, {%1, %1};" : "=l"(wv2) : "f"(wv));
        #pragma unroll
        for (int jg = 0; jg < 8; jg++) {
            ulonglong2 xv = *(const ulonglong2*)&sxT[k * 36 + jg * 4];
            FMA2(acc[jg * 2 + 0], xv.x, wv2);
            FMA2(acc[jg * 2 + 1], xv.y, wv2);
        }
    }

    float sA = a1s[col], sD = a1d[col];
    #pragma unroll
    for (int p = 0; p < 16; p++) {
        float lo, hi;
        asm("mov.b64 {%0, %1}, %2;" : "=f"(lo), "=f"(hi) : "l"(acc[p]));
        int n0 = nbase + p * 2;
        if (n0 < NN)     g_xl1h[(long)n0 * F1 + col]       = __float2half_rn(lo);
        if (n0 + 1 < NN) g_xl1h[(long)(n0 + 1) * F1 + col] = __float2half_rn(hi);
        float vs0 = lo * sA, vd0 = lo * sD, vs1 = hi * sA, vd1 = hi * sD;
        #pragma unroll
        for (int o = 16; o; o >>= 1) {
            vs0 += __shfl_xor_sync(0xffffffffu, vs0, o);
            vd0 += __shfl_xor_sync(0xffffffffu, vd0, o);
            vs1 += __shfl_xor_sync(0xffffffffu, vs1, o);
            vd1 += __shfl_xor_sync(0xffffffffu, vd1, o);
        }
        if (lane == 0 && n0 < NN) {
            g_asrc1[n0 * HEADS + wid] = vs0;
            g_adst1[n0 * HEADS + wid] = vd0;
            if (n0 + 1 < NN) {
                g_asrc1[(n0 + 1) * HEADS + wid] = vs1;
                g_adst1[(n0 + 1) * HEADS + wid] = vd1;
            }
        }
    }
}

// ---------------------------------------------------------------------------
// FUSED: gather layer1 (alpha/exp/aggregate) -> normalize+bias+ELU (h row in
// registers) -> h @ W2 via shuffles -> xl2 + layer2 attention dots.
// Warp per dst node; lane l holds h[4l..4l+3]; W2 staged in smem.
__global__ void __launch_bounds__(256) k_edge1l2(
    const float* __restrict__ bias1, const float* __restrict__ w2,
    const float* __restrict__ a2s, const float* __restrict__ a2d) {
    __shared__ float sw2[F1 * OUTC];   // 16KB
    for (int i = threadIdx.x; i < F1 * OUTC; i += 256) sw2[i] = w2[i];
    __syncthreads();

    int d = blockIdx.x * 8 + (threadIdx.x >> 5);
    if (d >= NN) return;
    int l = threadIdx.x & 31;
    int h = l >> 3;
    int beg = g_off[d], end = g_off[d + 1];
    float adst = g_adst1[d * HEADS + h];
    float cf = g_coef1[h];
    float4 acc = make_float4(0.f, 0.f, 0.f, 0.f);
    float den = 0.f;
    int j = beg;
    for (; j + 2 <= end; j += 2) {
        int2 e0 = g_es[j], e1 = g_es[j + 1];
        float as0 = g_asrc1[e0.x * HEADS + h];
        float as1 = g_asrc1[e1.x * HEADS + h];
        uint2 p0 = *(const uint2*)(g_xl1h + (long)e0.x * F1 + l * 4);
        uint2 p1 = *(const uint2*)(g_xl1h + (long)e1.x * F1 + l * 4);
        float al0 = as0 + adst + __int_as_float(e0.y) * cf;
        float al1 = as1 + adst + __int_as_float(e1.y) * cf;
        al0 = al0 > 0.f ? al0 : 0.2f * al0;
        al1 = al1 > 0.f ? al1 : 0.2f * al1;
        float ex0 = __expf(al0), ex1 = __expf(al1);
        den += ex0 + ex1;
        float2 a0 = __half22float2(*reinterpret_cast<__half2*>(&p0.x));
        float2 b0 = __half22float2(*reinterpret_cast<__half2*>(&p0.y));
        float2 a1 = __half22float2(*reinterpret_cast<__half2*>(&p1.x));
        float2 b1 = __half22float2(*reinterpret_cast<__half2*>(&p1.y));
        acc.x += ex0 * a0.x + ex1 * a1.x;
        acc.y += ex0 * a0.y + ex1 * a1.y;
        acc.z += ex0 * b0.x + ex1 * b1.x;
        acc.w += ex0 * b0.y + ex1 * b1.y;
    }
    if (j < end) {
        int2 e0 = g_es[j];
        float as0 = g_asrc1[e0.x * HEADS + h];
        uint2 p0 = *(const uint2*)(g_xl1h + (long)e0.x * F1 + l * 4);
        float al0 = as0 + adst + __int_as_float(e0.y) * cf;
        al0 = al0 > 0.f ? al0 : 0.2f * al0;
        float ex0 = __expf(al0);
        den += ex0;
        float2 a0 = __half22float2(*reinterpret_cast<__half2*>(&p0.x));
        float2 b0 = __half22float2(*reinterpret_cast<__half2*>(&p0.y));
        acc.x += ex0 * a0.x; acc.y += ex0 * a0.y;
        acc.z += ex0 * b0.x; acc.w += ex0 * b0.y;
    }
    float inv = 1.f / den;
    float4 b = *(const float4*)&bias1[l * 4];
    float4 v;
    v.x = acc.x * inv + b.x; v.y = acc.y * inv + b.y;
    v.z = acc.z * inv + b.z; v.w = acc.w * inv + b.w;
    v.x = v.x > 0.f ? v.x : expm1f(v.x);
    v.y = v.y > 0.f ? v.y : expm1f(v.y);
    v.z = v.z > 0.f ? v.z : expm1f(v.z);
    v.w = v.w > 0.f ? v.w : expm1f(v.w);

    // h @ W2: lane sl holds h[4sl..4sl+3]; output col = l
    float o2 = 0.f;
    #pragma unroll
    for (int sl = 0; sl < 32; sl++) {
        float h0 = __shfl_sync(0xffffffffu, v.x, sl);
        float h1 = __shfl_sync(0xffffffffu, v.y, sl);
        float h2 = __shfl_sync(0xffffffffu, v.z, sl);
        float h3 = __shfl_sync(0xffffffffu, v.w, sl);
        o2 += h0 * sw2[(sl * 4 + 0) * OUTC + l];
        o2 += h1 * sw2[(sl * 4 + 1) * OUTC + l];
        o2 += h2 * sw2[(sl * 4 + 2) * OUTC + l];
        o2 += h3 * sw2[(sl * 4 + 3) * OUTC + l];
    }
    g_xl2[d * OUTC + l] = o2;
    float vs = o2 * a2s[l], vd = o2 * a2d[l];
    #pragma unroll
    for (int o = 16; o; o >>= 1) {
        vs += __shfl_xor_sync(0xffffffffu, vs, o);
        vd += __shfl_xor_sync(0xffffffffu, vd, o);
    }
    if (l == 0) { g_asrc2[d] = vs; g_adst2[d] = vd; }
}

// ---------------------------------------------------------------------------
// Gather edge pass layer2: warp per dst node; lane = out col.
__global__ void __launch_bounds__(256) k_edge2g(float* __restrict__ out,
                                                const float* __restrict__ bias2) {
    int d = blockIdx.x * 8 + (threadIdx.x >> 5);
    if (d >= NN) return;
    int l = threadIdx.x & 31;
    int beg = g_off[d], end = g_off[d + 1];
    float adst = g_adst2[d];
    float cf = g_coef2;
    float acc = 0.f, den = 0.f;
    int j = beg;
    for (; j + 2 <= end; j += 2) {
        int2 e0 = g_es[j], e1 = g_es[j + 1];
        float as0 = g_asrc2[e0.x];
        float as1 = g_asrc2[e1.x];
        float v0 = g_xl2[e0.x * OUTC + l];
        float v1 = g_xl2[e1.x * OUTC + l];
        float al0 = as0 + adst + __int_as_float(e0.y) * cf;
        float al1 = as1 + adst + __int_as_float(e1.y) * cf;
        al0 = al0 > 0.f ? al0 : 0.2f * al0;
        al1 = al1 > 0.f ? al1 : 0.2f * al1;
        float ex0 = __expf(al0), ex1 = __expf(al1);
        den += ex0 + ex1;
        acc += ex0 * v0 + ex1 * v1;
    }
    if (j < end) {
        int2 e0 = g_es[j];
        float al0 = g_asrc2[e0.x] + adst + __int_as_float(e0.y) * cf;
        al0 = al0 > 0.f ? al0 : 0.2f * al0;
        float ex0 = __expf(al0);
        den += ex0;
        acc += ex0 * g_xl2[e0.x * OUTC + l];
    }
    out[(long)d * OUTC + l] = acc / den + bias2[l];
}

// ---------------------------------------------------------------------------
extern "C" void kernel_launch(void* const* d_in, const int* in_sizes, int n_in,
                              void* d_out, int out_size) {
    const float* x        = (const float*)d_in[0];
    const int*   eidx     = (const int*)  d_in[1];
    const float* eattr    = (const float*)d_in[2];
    const float* lin1_w   = (const float*)d_in[3];
    const float* att1_src = (const float*)d_in[4];
    const float* att1_dst = (const float*)d_in[5];
    const float* lin1_ew  = (const float*)d_in[6];
    const float* att1_e   = (const float*)d_in[7];
    const float* bias1    = (const float*)d_in[8];
    const float* lin2_w   = (const float*)d_in[9];
    const float* att2_src = (const float*)d_in[10];
    const float* att2_dst = (const float*)d_in[11];
    const float* lin2_ew  = (const float*)d_in[12];
    const float* att2_e   = (const float*)d_in[13];
    const float* bias2    = (const float*)d_in[14];
    float* out = (float*)d_out;

    static cudaStream_t sB = nullptr;
    static cudaEvent_t evFork = nullptr, evMisc = nullptr, evB = nullptr;
    static bool streamsOk = false;
    if (sB == nullptr && !streamsOk) {
        bool ok = (cudaStreamCreateWithFlags(&sB, cudaStreamNonBlocking) == cudaSuccess)
               && (cudaEventCreateWithFlags(&evFork, cudaEventDisableTiming) == cudaSuccess)
               && (cudaEventCreateWithFlags(&evMisc, cudaEventDisableTiming) == cudaSuccess)
               && (cudaEventCreateWithFlags(&evB, cudaEventDisableTiming) == cudaSuccess);
        streamsOk = ok;
        if (!ok) sB = nullptr;
    }

    if (streamsOk) {
        // fork side stream: easum/coef partials, then lin1 (independent of CSR)
        cudaEventRecord(evFork, 0);
        cudaStreamWaitEvent(sB, evFork, 0);
        k_prepmisc<<<512, 256, 0, sB>>>(eattr, lin1_ew, att1_e, lin2_ew, att2_e);
        cudaEventRecord(evMisc, sB);
        k_lin1<<<(NN + 31) / 32, 128, 0, sB>>>(x, lin1_w, att1_src, att1_dst);
        cudaEventRecord(evB, sB);

        // CSR build chain on the main stream
        k_zero<<<(NN + 255) / 256, 256>>>();
        k_hist<<<(ETOT / 4 + 255) / 256, 256>>>(eidx);
        k_scanA<<<SCAN_B, 1024>>>();
        cudaStreamWaitEvent(0, evMisc, 0);   // g_part ready for easum finalize
        k_scanB<<<1, 512>>>();
        k_scanC<<<SCAN_B, 1024>>>();
        k_scatter<<<(ETOT / 4 + 255) / 256, 256>>>(eidx, eattr);

        // join lin1, then fused edge1+lin2, then edge2
        cudaStreamWaitEvent(0, evB, 0);
        k_edge1l2<<<(NN + 7) / 8, 256>>>(bias1, lin2_w, att2_src, att2_dst);
        k_edge2g<<<(NN + 7) / 8, 256>>>(out, bias2);
    } else {
        // serial fallback (same kernels, one stream)
        k_prepmisc<<<512, 256>>>(eattr, lin1_ew, att1_e, lin2_ew, att2_e);
        k_lin1<<<(NN + 31) / 32, 128>>>(x, lin1_w, att1_src, att1_dst);
        k_zero<<<(NN + 255) / 256, 256>>>();
        k_hist<<<(ETOT / 4 + 255) / 256, 256>>>(eidx);
        k_scanA<<<SCAN_B, 1024>>>();
        k_scanB<<<1, 512>>>();
        k_scanC<<<SCAN_B, 1024>>>();
        k_scatter<<<(ETOT / 4 + 255) / 256, 256>>>(eidx, eattr);
        k_edge1l2<<<(NN + 7) / 8, 256>>>(bias1, lin2_w, att2_src, att2_dst);
        k_edge2g<<<(NN + 7) / 8, 256>>>(out, bias2);
    }
}